// round 14
// baseline (speedup 1.0000x reference)
#include <cuda_runtime.h>
#include <cuda_fp16.h>
#include <cstdint>

#define NN 50000
#define NE 300000
#define HD 256
#define NL 4
#define NBK 196   // ceil(NN/256)

// ---------------- scratch (static device globals; no allocs allowed) -------
__device__ float  g_h  [NN*HD];    // residual stream (fp32)
__device__ __half g_hh [NN*HD];    // residual stream mirror (half, for gather)
__device__ float  g_d2f[NN*HD];    // fp32 scratch: mm256 tmp, ee scatter
__device__ __half g_d1h[NN*HD];
__device__ __half g_d3h[NN*HD];
__device__ __half g_aeh[NN*HD];
__device__ __half g_xinh[NN*64];
__device__ float  g_deg[NN];
__device__ float  g_ps[24*HD];
__device__ float  g_pc[24];
__device__ __half g_wth[14*65536]; // half frags: 0 nin_w2, 1-4 M1, 5-8 E1, 9-12 upd_w2, 13 ee_w2
__device__ __half g_wt1h[16384];   // nin_w1 (K=64) half fragments
__device__ float  g_wtf[4*65536];  // fp32 tf32 frags: upd_w1 (mm256 only)
__device__ int    g_rp[NN+1];
__device__ int    g_cur[NN];
__device__ int    g_el[NE];
__device__ int    g_bs[256];

// ---------------- helpers ------------------------------------------------
__device__ __forceinline__ float tf32r(float x) {
    float r;
    asm("cvt.rna.tf32.f32 %0, %1;" : "=f"(r) : "f"(x));
    return r;
}
__device__ __forceinline__ void redAdd4(float* p, float4 v) {
    asm volatile("red.global.add.v4.f32 [%0], {%1,%2,%3,%4};"
                 :: "l"(p), "f"(v.x), "f"(v.y), "f"(v.z), "f"(v.w) : "memory");
}
__device__ __forceinline__ uint32_t smem_u32(const void* p) {
    uint32_t a;
    asm("{ .reg .u64 t; cvta.to.shared.u64 t, %1; cvt.u32.u64 %0, t; }"
        : "=r"(a) : "l"(p));
    return a;
}
__device__ __forceinline__ void cp_async16(uint32_t sdst, const void* gsrc) {
    asm volatile("cp.async.ca.shared.global [%0], [%1], 16;"
                 :: "r"(sdst), "l"(gsrc) : "memory");
}
#define CP_COMMIT() asm volatile("cp.async.commit_group;" ::: "memory")
#define CP_WAIT1()  asm volatile("cp.async.wait_group 1;" ::: "memory")

#define MMA_TF32(c, a, b0, b1)                                               \
    asm volatile("mma.sync.aligned.m16n8k8.row.col.f32.tf32.tf32.f32 "      \
        "{%0,%1,%2,%3}, {%4,%5,%6,%7}, {%8,%9}, {%0,%1,%2,%3};"             \
        : "+f"((c)[0]), "+f"((c)[1]), "+f"((c)[2]), "+f"((c)[3])            \
        : "r"((a)[0]), "r"((a)[1]), "r"((a)[2]), "r"((a)[3]),               \
          "r"(b0), "r"(b1))

#define MMA_F16(c, a, b0, b1)                                                \
    asm volatile("mma.sync.aligned.m16n8k16.row.col.f32.f16.f16.f32 "       \
        "{%0,%1,%2,%3}, {%4,%5,%6,%7}, {%8,%9}, {%0,%1,%2,%3};"             \
        : "+f"((c)[0]), "+f"((c)[1]), "+f"((c)[2]), "+f"((c)[3])            \
        : "r"((a)[0]), "r"((a)[1]), "r"((a)[2]), "r"((a)[3]),               \
          "r"(b0), "r"(b1))

struct WPtrs { const float* p[18]; };

// ---------------- fp32 weight -> tf32 lane-major fragment blocks -------------
__global__ void __launch_bounds__(256) wfrag_k(WPtrs wp, float* __restrict__ out) {
    const float* W = wp.p[blockIdx.y];
    float* O = out + (size_t)blockIdx.y * 65536 + blockIdx.x * 4096;
    const int kc = blockIdx.x >> 1, nb = blockIdx.x & 1;
    const int nl = threadIdx.x >> 1;
    const int khalf = (threadIdx.x & 1) * 16;
    const int n = nb * 128 + nl;
    #pragma unroll
    for (int g = 0; g < 4; ++g) {
        int kk0 = khalf + g * 4;
        int k = kc * 32 + kk0;
        float vv[4];
        vv[0] = tf32r(W[(size_t)(k+0)*256 + n]);
        vv[1] = tf32r(W[(size_t)(k+1)*256 + n]);
        vv[2] = tf32r(W[(size_t)(k+2)*256 + n]);
        vv[3] = tf32r(W[(size_t)(k+3)*256 + n]);
        int base = ((kk0>>3)*8 + (nl>>4))*128 + (nl&7)*16
                 + ((((nl>>3)&1)<<1) | ((kk0>>2)&1));
        #pragma unroll
        for (int q = 0; q < 4; ++q) O[base + q*4] = vv[q];
    }
}

// ---------------- fp32 weight -> f16 m16n8k16 fragment blocks ----------------
__global__ void __launch_bounds__(256) wfrag_h_k(WPtrs wp, __half* __restrict__ out) {
    const float* W = wp.p[blockIdx.y];
    __half* O = out + (size_t)blockIdx.y * 65536 + blockIdx.x * 4096;
    const int kc = blockIdx.x >> 1, nb = blockIdx.x & 1;
    const int nl = threadIdx.x >> 1;
    const int kp = (threadIdx.x & 1);
    const int n = nb * 128 + nl;
    const int group = kp * 16 + (nl >> 3);
    const int n8 = nl & 7;
    #pragma unroll
    for (int kk = 0; kk < 16; ++kk) {
        int k = kc * 32 + kp * 16 + kk;
        __half v = __float2half_rn(W[(size_t)k * 256 + n]);
        int lane = n8 * 4 + ((kk >> 1) & 3);
        int pos = group * 128 + lane * 4 + ((kk >> 3) << 1) + (kk & 1);
        O[pos] = v;
    }
}

__global__ void __launch_bounds__(256) wfrag64_h_k(
    const float* __restrict__ W, __half* __restrict__ out) {
    __half* O = out + blockIdx.x * 4096;
    const int kc = blockIdx.x >> 1, nb = blockIdx.x & 1;
    const int nl = threadIdx.x >> 1;
    const int kp = (threadIdx.x & 1);
    const int n = nb * 128 + nl;
    const int group = kp * 16 + (nl >> 3);
    const int n8 = nl & 7;
    #pragma unroll
    for (int kk = 0; kk < 16; ++kk) {
        int k = kc * 32 + kp * 16 + kk;
        __half v = __float2half_rn(W[(size_t)k * 256 + n]);
        int lane = n8 * 4 + ((kk >> 1) & 3);
        int pos = group * 128 + lane * 4 + ((kk >> 3) << 1) + (kk & 1);
        O[pos] = v;
    }
}

// ---------------- fp32 tf32 GEMM (mm256 precompute only) --------------------
#define GEMM_SMEM 98304

struct MMPtrs { const float* a[8]; };
__global__ void __launch_bounds__(256, 2) mm256_k(
    MMPtrs mp, const float* __restrict__ wtf, float* __restrict__ tmp)
{
    extern __shared__ float smf[];
    const uint32_t sbase = smem_u32(smf);
    const float* A = mp.a[blockIdx.z];
    const float* Wf = wtf + (size_t)(blockIdx.z & 3) * 65536;
    float* C = tmp + (size_t)blockIdx.z * 65536;
    const int nb = blockIdx.y;
    const int tid = threadIdx.x;
    const int wid = tid >> 5, lane = tid & 31;
    const int warp_m = wid & 1, warp_n = wid >> 1;
    const int bm = blockIdx.x * 128;

    const int a_row = tid >> 1;
    const int a_half = tid & 1;
    const int arow = bm + a_row;
    const int a_sw = a_row & 7;

    float acc[4][4][4];
    #pragma unroll
    for (int t = 0; t < 4; ++t)
        #pragma unroll
        for (int j = 0; j < 4; ++j)
            #pragma unroll
            for (int q = 0; q < 4; ++q) acc[t][j][q] = 0.f;

    auto cpA = [&](int c, int s) {
        const float* src = A + (size_t)arow * 256 + c * 32 + a_half * 16;
        uint32_t drow = sbase + s * 32768 + a_row * 128;
        #pragma unroll
        for (int j = 0; j < 4; ++j) {
            int chunk = a_half * 4 + j;
            cp_async16(drow + ((chunk ^ a_sw) << 4), src + j * 4);
        }
    };
    auto cpB = [&](int c, int s) {
        const float* src = Wf + ((size_t)c * 2 + nb) * 4096 + tid * 16;
        uint32_t dst = sbase + s * 32768 + 16384 + tid * 64;
        #pragma unroll
        for (int i = 0; i < 4; ++i)
            cp_async16(dst + i * 16, src + i * 4);
    };
    auto compute_ks = [&](int s, int ks) {
        const float* a = smf + s * 8192;
        const float* b = smf + s * 8192 + 4096;
        const int lr = lane >> 2, lc = lane & 3;
        uint32_t av[4][4];
        float4 bq[2];
        #pragma unroll
        for (int t = 0; t < 4; ++t) {
            int m0 = warp_m * 64 + t * 16 + lr;
            #pragma unroll
            for (int i = 0; i < 4; ++i) {
                int row = m0 + (i & 1) * 8;
                int chunk = 2 * ks + (i >> 1);
                float v = a[row * 32 + ((chunk ^ lr) << 2) + lc];
                av[t][i] = __float_as_uint(tf32r(v));
            }
        }
        #pragma unroll
        for (int p = 0; p < 2; ++p)
            bq[p] = *(const float4*)&b[((ks * 8 + warp_n * 2 + p) * 32 + lane) * 4];
        #pragma unroll
        for (int t = 0; t < 4; ++t)
            #pragma unroll
            for (int p = 0; p < 2; ++p) {
                MMA_TF32(acc[t][p*2+0], av[t],
                         __float_as_uint(bq[p].x), __float_as_uint(bq[p].y));
                MMA_TF32(acc[t][p*2+1], av[t],
                         __float_as_uint(bq[p].z), __float_as_uint(bq[p].w));
            }
    };

    #pragma unroll
    for (int s = 0; s < 2; ++s) { cpA(s, s); cpB(s, s); CP_COMMIT(); }
    for (int c = 0; c < 8; ++c) {
        CP_WAIT1();
        __syncthreads();
        int sl = c + 2;
        if (sl < 8) { cpA(sl, sl % 3); cpB(sl, sl % 3); }
        CP_COMMIT();
        int s = c % 3;
        compute_ks(s, 0); compute_ks(s, 1); compute_ks(s, 2); compute_ks(s, 3);
    }
    const int row_base = bm + warp_m * 64 + (lane >> 2);
    const int col_base = nb * 128 + warp_n * 32 + (lane & 3) * 2;
    #pragma unroll
    for (int t = 0; t < 4; ++t) {
        int r0 = row_base + t * 16, r1 = r0 + 8;
        #pragma unroll
        for (int j = 0; j < 4; ++j) {
            int col = col_base + j * 8;
            *(float2*)(C + (size_t)r0 * 256 + col) = make_float2(acc[t][j][0], acc[t][j][1]);
            *(float2*)(C + (size_t)r1 * 256 + col) = make_float2(acc[t][j][2], acc[t][j][3]);
        }
    }
}

// ---------------- fp16 m16n8k16 GEMM (split-N) --------------------------------
// CTA 128x128, 8 warps (2M x 4N), warp tile 64x32. K chunks of 32, 3 stages.
// OUTM: 0=float C, 1=half C, 2=float C + half C2
#define GEMM_H_SMEM 49152

template<int KROW, bool DUAL, bool RELU, int OUTM, bool ROWSCALE>
__global__ void __launch_bounds__(256, 2) gemm_h(
    const __half* __restrict__ A,  const __half* __restrict__ Wh,
    const __half* __restrict__ A2, const __half* __restrict__ Wh2,
    const float* __restrict__ bias, const float* __restrict__ rowscale,
    void* __restrict__ C, __half* __restrict__ C2, int M)
{
    extern __shared__ char smc[];
    const uint32_t sbase = smem_u32(smc);
    const int tid = threadIdx.x;
    const int wid = tid >> 5, lane = tid & 31;
    const int warp_m = wid & 1, warp_n = wid >> 1;
    const int bm = blockIdx.x * 128;
    const int nb = blockIdx.y;

    const int a_row = tid >> 1;
    const int a_part = tid & 1;
    const int arow = bm + a_row;
    const int a_sw = (a_row >> 1) & 3;

    float acc[4][4][4];
    #pragma unroll
    for (int t = 0; t < 4; ++t)
        #pragma unroll
        for (int j = 0; j < 4; ++j)
            #pragma unroll
            for (int q = 0; q < 4; ++q) acc[t][j][q] = 0.f;

    const int KC = KROW / 32;
    const int NCHUNK = (DUAL ? 2 : 1) * KC;

    auto cpA = [&](int c, int s) {
        const __half* Ap = (DUAL && c >= KC) ? A2 : A;
        int k0 = ((DUAL && c >= KC) ? (c - KC) : c) * 32;
        if (arow < M) {
            const __half* src = Ap + (size_t)arow * KROW + k0 + a_part * 16;
            uint32_t drow = sbase + s * 16384 + a_row * 64;
            #pragma unroll
            for (int j = 0; j < 2; ++j) {
                int ch = a_part * 2 + j;
                cp_async16(drow + ((ch ^ a_sw) << 4), src + j * 8);
            }
        } else {
            char* drow = smc + s * 16384 + a_row * 64;
            #pragma unroll
            for (int j = 0; j < 2; ++j) {
                int ch = a_part * 2 + j;
                *(uint4*)(drow + ((ch ^ a_sw) << 4)) = make_uint4(0,0,0,0);
            }
        }
    };
    auto cpB = [&](int c, int s) {
        const __half* Wp = (DUAL && c >= KC) ? Wh2 : Wh;
        int cc = (DUAL && c >= KC) ? (c - KC) : c;
        const __half* src = Wp + ((size_t)cc * 2 + nb) * 4096 + tid * 16;
        uint32_t dst = sbase + s * 16384 + 8192 + tid * 32;
        cp_async16(dst,      src);
        cp_async16(dst + 16, src + 8);
    };
    auto compute_ks = [&](int s, int ks) {
        const char* a = smc + s * 16384;
        const char* b = smc + s * 16384 + 8192;
        const int lr = lane >> 2, lc = lane & 3;
        uint32_t av[4][4];
        #pragma unroll
        for (int t = 0; t < 4; ++t) {
            int m0 = warp_m * 64 + t * 16 + lr;
            int m1 = m0 + 8;
            int sw0 = (m0 >> 1) & 3, sw1 = (m1 >> 1) & 3;
            av[t][0] = *(const uint32_t*)(a + m0*64 + (((2*ks  ) ^ sw0) << 4) + lc*4);
            av[t][1] = *(const uint32_t*)(a + m1*64 + (((2*ks  ) ^ sw1) << 4) + lc*4);
            av[t][2] = *(const uint32_t*)(a + m0*64 + (((2*ks+1) ^ sw0) << 4) + lc*4);
            av[t][3] = *(const uint32_t*)(a + m1*64 + (((2*ks+1) ^ sw1) << 4) + lc*4);
        }
        #pragma unroll
        for (int j = 0; j < 4; ++j) {
            uint2 q = *(const uint2*)(b + (ks*16 + warp_n*4 + j) * 256 + lane*8);
            #pragma unroll
            for (int t = 0; t < 4; ++t)
                MMA_F16(acc[t][j], av[t], q.x, q.y);
        }
    };

    #pragma unroll
    for (int s = 0; s < 2; ++s) {
        if (s < NCHUNK) { cpA(s, s); cpB(s, s); }
        CP_COMMIT();
    }
    for (int c = 0; c < NCHUNK; ++c) {
        CP_WAIT1();
        __syncthreads();
        int sl = c + 2;
        if (sl < NCHUNK) { cpA(sl, sl % 3); cpB(sl, sl % 3); }
        CP_COMMIT();
        int s = c % 3;
        compute_ks(s, 0);
        compute_ks(s, 1);
    }

    const int row_base = bm + warp_m * 64 + (lane >> 2);
    const int col_base = nb * 128 + warp_n * 32 + (lane & 3) * 2;
    #pragma unroll
    for (int t = 0; t < 4; ++t) {
        int r0 = row_base + t * 16;
        int r1 = r0 + 8;
        float s0 = 1.f, s1 = 1.f;
        if (ROWSCALE) {
            s0 = (r0 < M) ? rowscale[r0] : 0.f;
            s1 = (r1 < M) ? rowscale[r1] : 0.f;
        }
        #pragma unroll
        for (int j = 0; j < 4; ++j) {
            int col = col_base + j * 8;
            float bb0 = __ldg(bias + col), bb1 = __ldg(bias + col + 1);
            float v00 = acc[t][j][0] + bb0 * s0;
            float v01 = acc[t][j][1] + bb1 * s0;
            float v10 = acc[t][j][2] + bb0 * s1;
            float v11 = acc[t][j][3] + bb1 * s1;
            if (RELU) {
                v00 = fmaxf(v00, 0.f); v01 = fmaxf(v01, 0.f);
                v10 = fmaxf(v10, 0.f); v11 = fmaxf(v11, 0.f);
            }
            if (OUTM == 1) {
                __half* Ch = (__half*)C;
                if (r0 < M) *(__half2*)(Ch + (size_t)r0 * 256 + col) =
                    __floats2half2_rn(v00, v01);
                if (r1 < M) *(__half2*)(Ch + (size_t)r1 * 256 + col) =
                    __floats2half2_rn(v10, v11);
            } else {
                float* Cf = (float*)C;
                if (r0 < M) *(float2*)(Cf + (size_t)r0 * 256 + col) = make_float2(v00, v01);
                if (r1 < M) *(float2*)(Cf + (size_t)r1 * 256 + col) = make_float2(v10, v11);
                if (OUTM == 2) {
                    if (r0 < M) *(__half2*)(C2 + (size_t)r0 * 256 + col) =
                        __floats2half2_rn(v00, v01);
                    if (r1 < M) *(__half2*)(C2 + (size_t)r1 * 256 + col) =
                        __floats2half2_rn(v10, v11);
                }
            }
        }
    }
}

// ---------------- fused upd2 GEMM + residual + LayerNorm (fp16 mma) ----------
// CTA 64x256 full rows, 8 warps (2M x 4N), warp tile 32x64. 3-stage pipeline,
// stage = 4KB A + 16KB B = 20KB. u staged fp32 in smem [64][264], then LN.
#define GEMM_LN_SMEM 67584

__global__ void __launch_bounds__(256, 2) gemm_ln_h(
    const __half* __restrict__ A, const __half* __restrict__ Wh,
    const float* __restrict__ b2, const float* __restrict__ hin,
    const float* __restrict__ g, const float* __restrict__ b,
    float* __restrict__ ho, __half* __restrict__ hoh, int M)
{
    extern __shared__ char smc[];
    float* su = (float*)smc;
    const uint32_t sbase = smem_u32(smc);
    const int tid = threadIdx.x;
    const int wid = tid >> 5, lane = tid & 31;
    const int warp_m = wid & 1, warp_n = wid >> 1;   // 2M x 4N
    const int bm = blockIdx.x * 64;

    const int a_row = tid >> 2;          // 0..63
    const int a_part = tid & 3;
    const int arow = bm + a_row;
    const int a_sw = (a_row >> 1) & 3;

    float acc[2][8][4];
    #pragma unroll
    for (int t = 0; t < 2; ++t)
        #pragma unroll
        for (int j = 0; j < 8; ++j)
            #pragma unroll
            for (int q = 0; q < 4; ++q) acc[t][j][q] = 0.f;

    auto cpA = [&](int c, int s) {
        if (arow < M) {
            const __half* src = A + (size_t)arow * 256 + c * 32 + a_part * 8;
            uint32_t drow = sbase + s * 20480 + a_row * 64;
            cp_async16(drow + ((a_part ^ a_sw) << 4), src);
        } else {
            char* drow = smc + s * 20480 + a_row * 64;
            *(uint4*)(drow + ((a_part ^ a_sw) << 4)) = make_uint4(0,0,0,0);
        }
    };
    auto cpB = [&](int c, int s) {
        const __half* src = Wh + (size_t)c * 8192 + tid * 32;
        uint32_t dst = sbase + s * 20480 + 4096 + tid * 64;
        #pragma unroll
        for (int i = 0; i < 4; ++i)
            cp_async16(dst + i * 16, src + i * 8);
    };
    auto compute_ks = [&](int s, int ks) {
        const char* a = smc + s * 20480;
        const char* bb = smc + s * 20480 + 4096;
        const int lr = lane >> 2, lc = lane & 3;
        uint32_t av[2][4];
        #pragma unroll
        for (int t = 0; t < 2; ++t) {
            int m0 = warp_m * 32 + t * 16 + lr;
            int m1 = m0 + 8;
            int sw0 = (m0 >> 1) & 3, sw1 = (m1 >> 1) & 3;
            av[t][0] = *(const uint32_t*)(a + m0*64 + (((2*ks  ) ^ sw0) << 4) + lc*4);
            av[t][1] = *(const uint32_t*)(a + m1*64 + (((2*ks  ) ^ sw1) << 4) + lc*4);
            av[t][2] = *(const uint32_t*)(a + m0*64 + (((2*ks+1) ^ sw0) << 4) + lc*4);
            av[t][3] = *(const uint32_t*)(a + m1*64 + (((2*ks+1) ^ sw1) << 4) + lc*4);
        }
        const int nbk = warp_n >> 1;
        const int nt0 = (warp_n & 1) * 8;
        #pragma unroll
        for (int j = 0; j < 8; ++j) {
            uint2 q = *(const uint2*)(bb + nbk*8192 + (ks*16 + nt0 + j) * 256 + lane*8);
            #pragma unroll
            for (int t = 0; t < 2; ++t)
                MMA_F16(acc[t][j], av[t], q.x, q.y);
        }
    };

    cpA(0, 0); cpB(0, 0); CP_COMMIT();
    cpA(1, 1); cpB(1, 1); CP_COMMIT();
    for (int c = 0; c < 8; ++c) {
        CP_WAIT1();
        __syncthreads();
        int sl = c + 2;
        if (sl < 8) { cpA(sl, sl % 3); cpB(sl, sl % 3); }
        CP_COMMIT();
        int s = c % 3;
        compute_ks(s, 0);
        compute_ks(s, 1);
    }
    __syncthreads();   // pipeline smem now dead; reuse for u staging

    // ---- u = acc + b2 -> smem [64][264] ----
    {
        const int lr = lane >> 2;
        const int col_base = warp_n * 64 + (lane & 3) * 2;
        #pragma unroll
        for (int t = 0; t < 2; ++t) {
            int lr0 = warp_m * 32 + t * 16 + lr;
            int lr1 = lr0 + 8;
            #pragma unroll
            for (int j = 0; j < 8; ++j) {
                int col = col_base + j * 8;
                float bb0 = __ldg(b2 + col), bb1 = __ldg(b2 + col + 1);
                su[lr0 * 264 + col]     = acc[t][j][0] + bb0;
                su[lr0 * 264 + col + 1] = acc[t][j][1] + bb1;
                su[lr1 * 264 + col]     = acc[t][j][2] + bb0;
                su[lr1 * 264 + col + 1] = acc[t][j][3] + bb1;
            }
        }
    }
    __syncthreads();

    // ---- residual + LN: warp wid handles rows wid*8 .. wid*8+7 ----
    #pragma unroll 1
    for (int k = 0; k < 8; ++k) {
        int lrow = wid * 8 + k;
        int row = bm + lrow;
        if (row >= M) break;
        const float* hp = hin + (size_t)row * 256 + lane * 8;
        const float* up = su + lrow * 264 + lane * 8;
        float v[8];
        float4 h0 = *(const float4*)hp, h1 = *(const float4*)(hp + 4);
        float4 u0 = *(const float4*)up, u1 = *(const float4*)(up + 4);
        v[0]=h0.x+u0.x; v[1]=h0.y+u0.y; v[2]=h0.z+u0.z; v[3]=h0.w+u0.w;
        v[4]=h1.x+u1.x; v[5]=h1.y+u1.y; v[6]=h1.z+u1.z; v[7]=h1.w+u1.w;
        float s = 0.f;
        #pragma unroll
        for (int i = 0; i < 8; ++i) s += v[i];
        #pragma unroll
        for (int oo = 16; oo > 0; oo >>= 1) s += __shfl_xor_sync(0xffffffffu, s, oo);
        float mu = s * (1.f/256.f);
        float qq = 0.f;
        #pragma unroll
        for (int i = 0; i < 8; ++i) { float d = v[i]-mu; qq += d*d; }
        #pragma unroll
        for (int oo = 16; oo > 0; oo >>= 1) qq += __shfl_xor_sync(0xffffffffu, qq, oo);
        float rstd = rsqrtf(qq*(1.f/256.f) + 1e-5f);
        #pragma unroll
        for (int i = 0; i < 8; ++i) {
            int c = lane*8 + i;
            v[i] = (v[i]-mu)*rstd*__ldg(g+c) + __ldg(b+c);
        }
        float* op = ho + (size_t)row * 256 + lane * 8;
        *(float4*)op       = make_float4(v[0],v[1],v[2],v[3]);
        *(float4*)(op + 4) = make_float4(v[4],v[5],v[6],v[7]);
        if (hoh) {
            uint4 w;
            __half2* wp = (__half2*)&w;
            wp[0] = __floats2half2_rn(v[0], v[1]);
            wp[1] = __floats2half2_rn(v[2], v[3]);
            wp[2] = __floats2half2_rn(v[4], v[5]);
            wp[3] = __floats2half2_rn(v[6], v[7]);
            *(uint4*)(hoh + (size_t)row * 256 + lane * 8) = w;
        }
    }
}

// ---------------- f32 -> f16 elementwise (8 per thread) ----------------------
__global__ void __launch_bounds__(256) f2h_k(
    const float* __restrict__ in, __half* __restrict__ out, int n8)
{
    int i = blockIdx.x * 256 + threadIdx.x;
    if (i >= n8) return;
    float4 a = ((const float4*)in)[i*2];
    float4 b = ((const float4*)in)[i*2+1];
    uint4 o;
    __half2* op = (__half2*)&o;
    op[0] = __floats2half2_rn(a.x, a.y);
    op[1] = __floats2half2_rn(a.z, a.w);
    op[2] = __floats2half2_rn(b.x, b.y);
    op[3] = __floats2half2_rn(b.z, b.w);
    ((uint4*)out)[i] = o;
}

// ---------------- CSR build (by dst) -----------------------------------------
__global__ void __launch_bounds__(256) hist_k(
    const int* __restrict__ eidx, int* __restrict__ cnt) {
    int i = blockIdx.x * blockDim.x + threadIdx.x;
    if (i < NE) atomicAdd(&cnt[eidx[NE + i]], 1);
}

__global__ void __launch_bounds__(256) scan1_k(
    const int* __restrict__ cnt, int* __restrict__ bs) {
    __shared__ int sm[256];
    int i = blockIdx.x * 256 + threadIdx.x;
    sm[threadIdx.x] = (i < NN) ? cnt[i] : 0;
    __syncthreads();
    #pragma unroll
    for (int o = 128; o > 0; o >>= 1) {
        if (threadIdx.x < o) sm[threadIdx.x] += sm[threadIdx.x + o];
        __syncthreads();
    }
    if (threadIdx.x == 0) bs[blockIdx.x] = sm[0];
}

__global__ void __launch_bounds__(256) scan2_k(
    int* __restrict__ bs, int* __restrict__ rp) {
    __shared__ int sm[256];
    int t = threadIdx.x;
    int v = (t < NBK) ? bs[t] : 0;
    sm[t] = v;
    __syncthreads();
    #pragma unroll
    for (int o = 1; o < 256; o <<= 1) {
        int u = (t >= o) ? sm[t - o] : 0;
        __syncthreads();
        sm[t] += u;
        __syncthreads();
    }
    if (t < NBK) bs[t] = sm[t] - v;
    if (t == NBK - 1) rp[NN] = sm[t];
}

__global__ void __launch_bounds__(256) scan3_k(
    const int* __restrict__ bs, int* __restrict__ rp, int* __restrict__ cur) {
    __shared__ int sm[256];
    int i = blockIdx.x * 256 + threadIdx.x;
    int v = (i < NN) ? cur[i] : 0;
    sm[threadIdx.x] = v;
    __syncthreads();
    #pragma unroll
    for (int o = 1; o < 256; o <<= 1) {
        int u = (threadIdx.x >= o) ? sm[threadIdx.x - o] : 0;
        __syncthreads();
        sm[threadIdx.x] += u;
        __syncthreads();
    }
    if (i < NN) {
        int off = bs[blockIdx.x] + sm[threadIdx.x] - v;
        rp[i] = off;
        cur[i] = off;
    }
}

__global__ void __launch_bounds__(256) scatter_k(
    const int* __restrict__ eidx, int* __restrict__ cur, int* __restrict__ el) {
    int e = blockIdx.x * blockDim.x + threadIdx.x;
    if (e < NE) {
        int pos = atomicAdd(&cur[eidx[NE + e]], 1);
        el[pos] = eidx[e];
    }
}

// ---------------- SpMM gather: half h -> half agg (4-edge unroll) ------------
__global__ void __launch_bounds__(256) spmm_gather_k(
    const __half* __restrict__ hh, const int* __restrict__ rp,
    const int* __restrict__ el, __half* __restrict__ agg)
{
    int n = (blockIdx.x * 256 + threadIdx.x) >> 5;
    if (n >= NN) return;
    const int lane = threadIdx.x & 31;
    const int c = lane * 8;
    int s = rp[n], e = rp[n + 1];
    float a0 = 0.f, a1 = 0.f, a2 = 0.f, a3 = 0.f;
    float a4 = 0.f, a5 = 0.f, a6 = 0.f, a7 = 0.f;
    auto addrow = [&](uint4 r) {
        __half2* p = (__half2*)&r;
        float2 f0 = __half22float2(p[0]);
        float2 f1 = __half22float2(p[1]);
        float2 f2 = __half22float2(p[2]);
        float2 f3 = __half22float2(p[3]);
        a0 += f0.x; a1 += f0.y; a2 += f1.x; a3 += f1.y;
        a4 += f2.x; a5 += f2.y; a6 += f3.x; a7 += f3.y;
    };
    int i = s;
    for (; i + 3 < e; i += 4) {
        int s0 = __ldg(el + i),     s1 = __ldg(el + i + 1);
        int s2 = __ldg(el + i + 2), s3 = __ldg(el + i + 3);
        uint4 r0 = *(const uint4*)(hh + (size_t)s0 * 256 + c);
        uint4 r1 = *(const uint4*)(hh + (size_t)s1 * 256 + c);
        uint4 r2 = *(const uint4*)(hh + (size_t)s2 * 256 + c);
        uint4 r3 = *(const uint4*)(hh + (size_t)s3 * 256 + c);
        addrow(r0); addrow(r1); addrow(r2); addrow(r3);
    }
    for (; i < e; ++i) {
        uint4 r = *(const uint4*)(hh + (size_t)__ldg(el + i) * 256 + c);
        addrow(r);
    }
    uint4 o;
    __half2* op = (__half2*)&o;
    op[0] = __floats2half2_rn(a0, a1);
    op[1] = __floats2half2_rn(a2, a3);
    op[2] = __floats2half2_rn(a4, a5);
    op[3] = __floats2half2_rn(a6, a7);
    *(uint4*)(agg + (size_t)n * 256 + c) = o;
}

// ---------------- geo stage -> half xin ----------------------------------------
__global__ void __launch_bounds__(256) geo_k(
    const float* __restrict__ x,
    const float* __restrict__ geo_w, const float* __restrict__ geo_b,
    __half* __restrict__ out)
{
    __shared__ float gws[4096];
    __shared__ float gbs[32];
    for (int i = threadIdx.x; i < 4096; i += 256) gws[i] = geo_w[i];
    if (threadIdx.x < 32) gbs[threadIdx.x] = geo_b[threadIdx.x];
    __syncthreads();
    const int warp = threadIdx.x >> 5, lane = threadIdx.x & 31;
    for (int n0 = blockIdx.x * 8; n0 < NN; n0 += gridDim.x * 8) {
        int n = n0 + warp;
        if (n < NN) {
            const float* xr = x + (size_t)n * 160;
            float s = gbs[lane];
            #pragma unroll
            for (int k = 0; k < 128; ++k) s += __ldg(xr + k) * gws[k * 32 + lane];
            out[(size_t)n * 64 + lane]      = __float2half_rn(fmaxf(s, 0.f));
            out[(size_t)n * 64 + 32 + lane] = __float2half_rn(__ldg(xr + 128 + lane));
        }
    }
}

// ---------------- edge encoder + scatter (fp32, 16 edges per sync) -----------
__global__ void __launch_bounds__(256) edge_encode_k(
    const float* __restrict__ ea, const int* __restrict__ eidx,
    const float* __restrict__ w1, const float* __restrict__ b1,
    float* __restrict__ At, float* __restrict__ deg)
{
    const int tid = threadIdx.x;
    const int c0 = (tid & 63) * 4;
    const int slot = tid >> 6;
    float4 wreg[16];
    #pragma unroll
    for (int k = 0; k < 16; ++k)
        wreg[k] = *(const float4*)(w1 + k * 256 + c0);
    const float4 b1v = *(const float4*)(b1 + c0);

    __shared__ float eav[16][16];
    __shared__ int dsts[16];

    for (int base = blockIdx.x * 16; base < NE; base += gridDim.x * 16) {
        ((float*)eav)[tid] = ea[(size_t)base * 16 + tid];
        if (tid < 16) dsts[tid] = eidx[NE + base + tid];
        __syncthreads();
        #pragma unroll
        for (int g = 0; g < 4; ++g) {
            const int e = slot + g * 4;
            float4 acc = b1v;
            #pragma unroll
            for (int k = 0; k < 16; ++k) {
                float ev = eav[e][k];
                acc.x += wreg[k].x * ev;
                acc.y += wreg[k].y * ev;
                acc.z += wreg[k].z * ev;
                acc.w += wreg[k].w * ev;
            }
            acc.x = fmaxf(acc.x, 0.f); acc.y = fmaxf(acc.y, 0.f);
            acc.z = fmaxf(acc.z, 0.f); acc.w = fmaxf(acc.w, 0.f);
            int dst = dsts[e];
            redAdd4(At + (size_t)dst * 256 + c0, acc);
            if ((tid & 63) == 0) atomicAdd(deg + dst, 1.f);
        }
        __syncthreads();
    }
}

// ---------------- typed mean-pool partial sums -------------------------------
__global__ void __launch_bounds__(256) pool_k(
    const float* __restrict__ h, const int* __restrict__ batch,
    const int* __restrict__ ntype, float* __restrict__ ps, float* __restrict__ pc)
{
    __shared__ float acc[24][256];
    __shared__ float cnt[24];
    for (int i = threadIdx.x; i < 24*256; i += 256) (&acc[0][0])[i] = 0.f;
    if (threadIdx.x < 24) cnt[threadIdx.x] = 0.f;
    __syncthreads();
    int per = (NN + gridDim.x - 1) / gridDim.x;
    int start = blockIdx.x * per;
    int end = start + per; if (end > NN) end = NN;
    for (int n = start; n < end; ++n) {
        int idx = __ldg(ntype+n)*8 + __ldg(batch+n);
        acc[idx][threadIdx.x] += h[(size_t)n*256 + threadIdx.x];
        if (threadIdx.x == 0) cnt[idx] += 1.f;
    }
    __syncthreads();
    for (int i = threadIdx.x; i < 24*256; i += 256) atomicAdd(&ps[i], (&acc[0][0])[i]);
    if (threadIdx.x < 24) atomicAdd(&pc[threadIdx.x], cnt[threadIdx.x]);
}

// ---------------- small writeout: z + batch only ------------------------------
__global__ void __launch_bounds__(256) writeout_small_k(
    const float* __restrict__ ps, const float* __restrict__ pc,
    const int* __restrict__ batch, float* __restrict__ out, int out_size)
{
    const int total = 6144 + NN;
    int i = blockIdx.x * blockDim.x + threadIdx.x;
    if (i >= total) return;
    float v; int o;
    if (i < 6144) {
        int c = i & 255, kb = i >> 8, k = kb >> 3, bb = kb & 7;
        float cc = pc[kb]; if (cc < 1.f) cc = 1.f;
        v = ps[i] / cc;
        o = bb*768 + k*256 + c;
    } else {
        v = (float)batch[i - 6144];
        o = 6144 + NN*HD + (i - 6144);
    }
    if (o < out_size) out[o] = v;
}

// ---------------- launcher ----------------------------------------------------
extern "C" void kernel_launch(void* const* d_in, const int* in_sizes, int n_in,
                              void* d_out, int out_size)
{
    const float* x       = (const float*)d_in[0];
    const float* ea      = (const float*)d_in[1];
    const float* geo_w   = (const float*)d_in[2];
    const float* geo_b   = (const float*)d_in[3];
    const float* nin_w1  = (const float*)d_in[4];
    const float* nin_b1  = (const float*)d_in[5];
    const float* nin_w2  = (const float*)d_in[6];
    const float* nin_b2  = (const float*)d_in[7];
    const float* ee_w1   = (const float*)d_in[8];
    const float* ee_b1   = (const float*)d_in[9];
    const float* ee_w2   = (const float*)d_in[10];
    const float* ee_b2   = (const float*)d_in[11];
    const float* msgx    = (const float*)d_in[12];
    const float* msge    = (const float*)d_in[13];
    const float* upd_w1  = (const float*)d_in[14];
    const float* upd_b1  = (const float*)d_in[15];
    const float* upd_w2  = (const float*)d_in[16];
    const float* upd_b2  = (const float*)d_in[17];
    const float* ln_g    = (const float*)d_in[18];
    const float* ln_b    = (const float*)d_in[19];
    const int*   eidx    = (const int*)d_in[20];
    const int*   batch   = (const int*)d_in[21];
    const int*   ntype   = (const int*)d_in[22];
    float* out = (float*)d_out;

    float *h_, *d2f_, *deg_, *ps_, *pc_, *wtf_;
    __half *hh_, *d1h_, *d3h_, *aeh_, *xinh_, *wth_, *wt1h_;
    int *rp_, *cur_, *el_, *bs_;
    cudaGetSymbolAddress((void**)&h_,   g_h);
    cudaGetSymbolAddress((void**)&hh_,  g_hh);
    cudaGetSymbolAddress((void**)&d2f_, g_d2f);
    cudaGetSymbolAddress((void**)&deg_, g_deg);
    cudaGetSymbolAddress((void**)&ps_,  g_ps);
    cudaGetSymbolAddress((void**)&pc_,  g_pc);
    cudaGetSymbolAddress((void**)&wtf_, g_wtf);
    cudaGetSymbolAddress((void**)&d1h_, g_d1h);
    cudaGetSymbolAddress((void**)&d3h_, g_d3h);
    cudaGetSymbolAddress((void**)&aeh_, g_aeh);
    cudaGetSymbolAddress((void**)&xinh_, g_xinh);
    cudaGetSymbolAddress((void**)&wth_, g_wth);
    cudaGetSymbolAddress((void**)&wt1h_, g_wt1h);
    cudaGetSymbolAddress((void**)&rp_,  g_rp);
    cudaGetSymbolAddress((void**)&cur_, g_cur);
    cudaGetSymbolAddress((void**)&el_,  g_el);
    cudaGetSymbolAddress((void**)&bs_,  g_bs);

    cudaFuncSetAttribute((const void*)mm256_k,
        cudaFuncAttributeMaxDynamicSharedMemorySize, GEMM_SMEM);
    cudaFuncSetAttribute((const void*)gemm_h<64,false,true,1,false>,
        cudaFuncAttributeMaxDynamicSharedMemorySize, GEMM_H_SMEM);
    cudaFuncSetAttribute((const void*)gemm_h<256,false,false,2,false>,
        cudaFuncAttributeMaxDynamicSharedMemorySize, GEMM_H_SMEM);
    cudaFuncSetAttribute((const void*)gemm_h<256,false,false,1,true>,
        cudaFuncAttributeMaxDynamicSharedMemorySize, GEMM_H_SMEM);
    cudaFuncSetAttribute((const void*)gemm_h<256,true,true,1,false>,
        cudaFuncAttributeMaxDynamicSharedMemorySize, GEMM_H_SMEM);
    cudaFuncSetAttribute((const void*)gemm_ln_h,
        cudaFuncAttributeMaxDynamicSharedMemorySize, GEMM_LN_SMEM);

    // --- weight precompute ----------------------------------------------------
    WPtrs wpf;
    for (int l = 0; l < 4; ++l) wpf.p[l] = upd_w1 + (size_t)l*65536;
    wfrag_k<<<dim3(16, 4), 256>>>(wpf, wtf_);

    MMPtrs mp;
    for (int l = 0; l < 4; ++l) {
        mp.a[l]     = msgx + (size_t)l*65536;
        mp.a[4 + l] = msge + (size_t)l*65536;
    }
    mm256_k<<<dim3(2, 2, 8), 256, GEMM_SMEM>>>(mp, wtf_, d2f_);

    WPtrs wph;
    wph.p[0] = nin_w2;
    for (int l = 0; l < 4; ++l) {
        wph.p[1 + l] = d2f_ + (size_t)l*65536;
        wph.p[5 + l] = d2f_ + (size_t)(4+l)*65536;
        wph.p[9 + l] = upd_w2 + (size_t)l*65536;
    }
    wph.p[13] = ee_w2;
    wfrag_h_k<<<dim3(16, 14), 256>>>(wph, wth_);
    wfrag64_h_k<<<4, 256>>>(nin_w1, wt1h_);

    // --- CSR build (by dst) -----------------------------------------------------
    cudaMemsetAsync(cur_, 0, NN*sizeof(int));
    hist_k<<<(NE+255)/256, 256>>>(eidx, cur_);
    scan1_k<<<NBK, 256>>>(cur_, bs_);
    scan2_k<<<1, 256>>>(bs_, rp_);
    scan3_k<<<NBK, 256>>>(bs_, rp_, cur_);
    scatter_k<<<(NE+255)/256, 256>>>(eidx, cur_, el_);

    dim3 gg(391, 2);

    // node encoder
    geo_k<<<625, 256>>>(x, geo_w, geo_b, xinh_);
    gemm_h<64,false,true,1,false><<<gg, 256, GEMM_H_SMEM>>>(
        xinh_, wt1h_, nullptr, nullptr, nin_b1, nullptr, d1h_, nullptr, NN);
    gemm_h<256,false,false,2,false><<<gg, 256, GEMM_H_SMEM>>>(
        d1h_, wth_ + (size_t)0*65536, nullptr, nullptr, nin_b2, nullptr,
        h_, hh_, NN);

    // edge encoder scatter (fp32) -> convert to half -> ee GEMM -> aeh
    cudaMemsetAsync(d2f_, 0, (size_t)NN*HD*sizeof(float));
    cudaMemsetAsync(deg_, 0, (size_t)NN*sizeof(float));
    edge_encode_k<<<1184, 256>>>(ea, eidx, ee_w1, ee_b1, d2f_, deg_);
    f2h_k<<<(NN*HD/8+255)/256, 256>>>(d2f_, d1h_, NN*HD/8);
    gemm_h<256,false,false,1,true><<<gg, 256, GEMM_H_SMEM>>>(
        d1h_, wth_ + (size_t)13*65536, nullptr, nullptr, ee_b2, deg_,
        aeh_, nullptr, NN);

    float* hout = out + 6144;
    for (int l = 0; l < NL; ++l) {
        spmm_gather_k<<<6250, 256>>>(hh_, rp_, el_, d1h_);
        // d3h = relu(Ah@M1 + Ae@E1 + b1)
        gemm_h<256,true,true,1,false><<<gg, 256, GEMM_H_SMEM>>>(
            d1h_, wth_ + (size_t)(1+l)*65536, aeh_, wth_ + (size_t)(5+l)*65536,
            upd_b1 + l*256, nullptr, d3h_, nullptr, NN);
        // h = LN(h + d3h@upd_w2 + b2)   [fused upd2 + residual + LN]
        gemm_ln_h<<<782, 256, GEMM_LN_SMEM>>>(
            d3h_, wth_ + (size_t)(9+l)*65536, upd_b2 + l*256, h_,
            ln_g + l*256, ln_b + l*256,
            (l == NL-1) ? hout : h_,
            (l == NL-1) ? nullptr : hh_, NN);
    }

    cudaMemsetAsync(ps_, 0, 24*HD*sizeof(float));
    cudaMemsetAsync(pc_, 0, 24*sizeof(float));
    pool_k<<<512, 256>>>(hout, batch, ntype, ps_, pc_);
    writeout_small_k<<<(6144+NN+255)/256, 256>>>(ps_, pc_, batch, out, out_size);
}

// round 15
// speedup vs baseline: 1.0107x; 1.0107x over previous
#include <cuda_runtime.h>
#include <cuda_fp16.h>
#include <cstdint>

#define NN 50000
#define NE 300000
#define HD 256
#define NL 4
#define NBK 196   // ceil(NN/256)

// ---------------- scratch (static device globals; no allocs allowed) -------
__device__ float  g_h  [NN*HD];    // residual stream (fp32)
__device__ __half g_hh [NN*HD];    // residual stream mirror (half, for gather)
__device__ float  g_d2f[NN*HD];    // fp32 scratch: mm256 tmp, ee scatter
__device__ __half g_d1h[NN*HD];
__device__ __half g_d3h[NN*HD];
__device__ __half g_aeh[NN*HD];
__device__ __half g_xinh[NN*64];
__device__ float  g_deg[NN];
__device__ float  g_ps[24*HD];
__device__ float  g_pc[24];
__device__ __half g_wth[14*65536]; // half frags: 0 nin_w2, 1-4 M1, 5-8 E1, 9-12 upd_w2, 13 ee_w2
__device__ __half g_wt1h[16384];   // nin_w1 (K=64) half fragments
__device__ float  g_wtf[4*65536];  // fp32 tf32 frags: upd_w1 (mm256 only)
__device__ int    g_rp[NN+1];
__device__ int    g_cur[NN];
__device__ int    g_el[NE];
__device__ int    g_bs[256];

// ---------------- helpers ------------------------------------------------
__device__ __forceinline__ float tf32r(float x) {
    float r;
    asm("cvt.rna.tf32.f32 %0, %1;" : "=f"(r) : "f"(x));
    return r;
}
__device__ __forceinline__ void redAdd4(float* p, float4 v) {
    asm volatile("red.global.add.v4.f32 [%0], {%1,%2,%3,%4};"
                 :: "l"(p), "f"(v.x), "f"(v.y), "f"(v.z), "f"(v.w) : "memory");
}
__device__ __forceinline__ uint32_t smem_u32(const void* p) {
    uint32_t a;
    asm("{ .reg .u64 t; cvta.to.shared.u64 t, %1; cvt.u32.u64 %0, t; }"
        : "=r"(a) : "l"(p));
    return a;
}
__device__ __forceinline__ void cp_async16(uint32_t sdst, const void* gsrc) {
    asm volatile("cp.async.ca.shared.global [%0], [%1], 16;"
                 :: "r"(sdst), "l"(gsrc) : "memory");
}
#define CP_COMMIT() asm volatile("cp.async.commit_group;" ::: "memory")
#define CP_WAIT1()  asm volatile("cp.async.wait_group 1;" ::: "memory")

#define MMA_TF32(c, a, b0, b1)                                               \
    asm volatile("mma.sync.aligned.m16n8k8.row.col.f32.tf32.tf32.f32 "      \
        "{%0,%1,%2,%3}, {%4,%5,%6,%7}, {%8,%9}, {%0,%1,%2,%3};"             \
        : "+f"((c)[0]), "+f"((c)[1]), "+f"((c)[2]), "+f"((c)[3])            \
        : "r"((a)[0]), "r"((a)[1]), "r"((a)[2]), "r"((a)[3]),               \
          "r"(b0), "r"(b1))

#define MMA_F16(c, a, b0, b1)                                                \
    asm volatile("mma.sync.aligned.m16n8k16.row.col.f32.f16.f16.f32 "       \
        "{%0,%1,%2,%3}, {%4,%5,%6,%7}, {%8,%9}, {%0,%1,%2,%3};"             \
        : "+f"((c)[0]), "+f"((c)[1]), "+f"((c)[2]), "+f"((c)[3])            \
        : "r"((a)[0]), "r"((a)[1]), "r"((a)[2]), "r"((a)[3]),               \
          "r"(b0), "r"(b1))

struct WPtrs { const float* p[18]; };

// ---------------- fp32 weight -> tf32 lane-major fragment blocks -------------
__global__ void __launch_bounds__(256) wfrag_k(WPtrs wp, float* __restrict__ out) {
    const float* W = wp.p[blockIdx.y];
    float* O = out + (size_t)blockIdx.y * 65536 + blockIdx.x * 4096;
    const int kc = blockIdx.x >> 1, nb = blockIdx.x & 1;
    const int nl = threadIdx.x >> 1;
    const int khalf = (threadIdx.x & 1) * 16;
    const int n = nb * 128 + nl;
    #pragma unroll
    for (int g = 0; g < 4; ++g) {
        int kk0 = khalf + g * 4;
        int k = kc * 32 + kk0;
        float vv[4];
        vv[0] = tf32r(W[(size_t)(k+0)*256 + n]);
        vv[1] = tf32r(W[(size_t)(k+1)*256 + n]);
        vv[2] = tf32r(W[(size_t)(k+2)*256 + n]);
        vv[3] = tf32r(W[(size_t)(k+3)*256 + n]);
        int base = ((kk0>>3)*8 + (nl>>4))*128 + (nl&7)*16
                 + ((((nl>>3)&1)<<1) | ((kk0>>2)&1));
        #pragma unroll
        for (int q = 0; q < 4; ++q) O[base + q*4] = vv[q];
    }
}

// ---------------- fp32 weight -> f16 m16n8k16 fragment blocks ----------------
__global__ void __launch_bounds__(256) wfrag_h_k(WPtrs wp, __half* __restrict__ out) {
    const float* W = wp.p[blockIdx.y];
    __half* O = out + (size_t)blockIdx.y * 65536 + blockIdx.x * 4096;
    const int kc = blockIdx.x >> 1, nb = blockIdx.x & 1;
    const int nl = threadIdx.x >> 1;
    const int kp = (threadIdx.x & 1);
    const int n = nb * 128 + nl;
    const int group = kp * 16 + (nl >> 3);
    const int n8 = nl & 7;
    #pragma unroll
    for (int kk = 0; kk < 16; ++kk) {
        int k = kc * 32 + kp * 16 + kk;
        __half v = __float2half_rn(W[(size_t)k * 256 + n]);
        int lane = n8 * 4 + ((kk >> 1) & 3);
        int pos = group * 128 + lane * 4 + ((kk >> 3) << 1) + (kk & 1);
        O[pos] = v;
    }
}

__global__ void __launch_bounds__(256) wfrag64_h_k(
    const float* __restrict__ W, __half* __restrict__ out) {
    __half* O = out + blockIdx.x * 4096;
    const int kc = blockIdx.x >> 1, nb = blockIdx.x & 1;
    const int nl = threadIdx.x >> 1;
    const int kp = (threadIdx.x & 1);
    const int n = nb * 128 + nl;
    const int group = kp * 16 + (nl >> 3);
    const int n8 = nl & 7;
    #pragma unroll
    for (int kk = 0; kk < 16; ++kk) {
        int k = kc * 32 + kp * 16 + kk;
        __half v = __float2half_rn(W[(size_t)k * 256 + n]);
        int lane = n8 * 4 + ((kk >> 1) & 3);
        int pos = group * 128 + lane * 4 + ((kk >> 3) << 1) + (kk & 1);
        O[pos] = v;
    }
}

// ---------------- fp32 tf32 GEMM (mm256 precompute only) --------------------
#define GEMM_SMEM 98304

struct MMPtrs { const float* a[8]; };
__global__ void __launch_bounds__(256, 2) mm256_k(
    MMPtrs mp, const float* __restrict__ wtf, float* __restrict__ tmp)
{
    extern __shared__ float smf[];
    const uint32_t sbase = smem_u32(smf);
    const float* A = mp.a[blockIdx.z];
    const float* Wf = wtf + (size_t)(blockIdx.z & 3) * 65536;
    float* C = tmp + (size_t)blockIdx.z * 65536;
    const int nb = blockIdx.y;
    const int tid = threadIdx.x;
    const int wid = tid >> 5, lane = tid & 31;
    const int warp_m = wid & 1, warp_n = wid >> 1;
    const int bm = blockIdx.x * 128;

    const int a_row = tid >> 1;
    const int a_half = tid & 1;
    const int arow = bm + a_row;
    const int a_sw = a_row & 7;

    float acc[4][4][4];
    #pragma unroll
    for (int t = 0; t < 4; ++t)
        #pragma unroll
        for (int j = 0; j < 4; ++j)
            #pragma unroll
            for (int q = 0; q < 4; ++q) acc[t][j][q] = 0.f;

    auto cpA = [&](int c, int s) {
        const float* src = A + (size_t)arow * 256 + c * 32 + a_half * 16;
        uint32_t drow = sbase + s * 32768 + a_row * 128;
        #pragma unroll
        for (int j = 0; j < 4; ++j) {
            int chunk = a_half * 4 + j;
            cp_async16(drow + ((chunk ^ a_sw) << 4), src + j * 4);
        }
    };
    auto cpB = [&](int c, int s) {
        const float* src = Wf + ((size_t)c * 2 + nb) * 4096 + tid * 16;
        uint32_t dst = sbase + s * 32768 + 16384 + tid * 64;
        #pragma unroll
        for (int i = 0; i < 4; ++i)
            cp_async16(dst + i * 16, src + i * 4);
    };
    auto compute_ks = [&](int s, int ks) {
        const float* a = smf + s * 8192;
        const float* b = smf + s * 8192 + 4096;
        const int lr = lane >> 2, lc = lane & 3;
        uint32_t av[4][4];
        float4 bq[2];
        #pragma unroll
        for (int t = 0; t < 4; ++t) {
            int m0 = warp_m * 64 + t * 16 + lr;
            #pragma unroll
            for (int i = 0; i < 4; ++i) {
                int row = m0 + (i & 1) * 8;
                int chunk = 2 * ks + (i >> 1);
                float v = a[row * 32 + ((chunk ^ lr) << 2) + lc];
                av[t][i] = __float_as_uint(tf32r(v));
            }
        }
        #pragma unroll
        for (int p = 0; p < 2; ++p)
            bq[p] = *(const float4*)&b[((ks * 8 + warp_n * 2 + p) * 32 + lane) * 4];
        #pragma unroll
        for (int t = 0; t < 4; ++t)
            #pragma unroll
            for (int p = 0; p < 2; ++p) {
                MMA_TF32(acc[t][p*2+0], av[t],
                         __float_as_uint(bq[p].x), __float_as_uint(bq[p].y));
                MMA_TF32(acc[t][p*2+1], av[t],
                         __float_as_uint(bq[p].z), __float_as_uint(bq[p].w));
            }
    };

    #pragma unroll
    for (int s = 0; s < 2; ++s) { cpA(s, s); cpB(s, s); CP_COMMIT(); }
    for (int c = 0; c < 8; ++c) {
        CP_WAIT1();
        __syncthreads();
        int sl = c + 2;
        if (sl < 8) { cpA(sl, sl % 3); cpB(sl, sl % 3); }
        CP_COMMIT();
        int s = c % 3;
        compute_ks(s, 0); compute_ks(s, 1); compute_ks(s, 2); compute_ks(s, 3);
    }
    const int row_base = bm + warp_m * 64 + (lane >> 2);
    const int col_base = nb * 128 + warp_n * 32 + (lane & 3) * 2;
    #pragma unroll
    for (int t = 0; t < 4; ++t) {
        int r0 = row_base + t * 16, r1 = r0 + 8;
        #pragma unroll
        for (int j = 0; j < 4; ++j) {
            int col = col_base + j * 8;
            *(float2*)(C + (size_t)r0 * 256 + col) = make_float2(acc[t][j][0], acc[t][j][1]);
            *(float2*)(C + (size_t)r1 * 256 + col) = make_float2(acc[t][j][2], acc[t][j][3]);
        }
    }
}

// ---------------- fp16 m16n8k16 GEMM (split-N) --------------------------------
// CTA 128x128, 8 warps (2M x 4N), warp tile 64x32. K chunks of 32, 3 stages.
// OUTM: 0=float C, 1=half C, 2=float C + half C2
#define GEMM_H_SMEM 49152

template<int KROW, bool DUAL, bool RELU, int OUTM, bool ROWSCALE>
__global__ void __launch_bounds__(256, 2) gemm_h(
    const __half* __restrict__ A,  const __half* __restrict__ Wh,
    const __half* __restrict__ A2, const __half* __restrict__ Wh2,
    const float* __restrict__ bias, const float* __restrict__ rowscale,
    void* __restrict__ C, __half* __restrict__ C2, int M)
{
    extern __shared__ char smc[];
    const uint32_t sbase = smem_u32(smc);
    const int tid = threadIdx.x;
    const int wid = tid >> 5, lane = tid & 31;
    const int warp_m = wid & 1, warp_n = wid >> 1;
    const int bm = blockIdx.x * 128;
    const int nb = blockIdx.y;

    const int a_row = tid >> 1;
    const int a_part = tid & 1;
    const int arow = bm + a_row;
    const int a_sw = (a_row >> 1) & 3;

    float acc[4][4][4];
    #pragma unroll
    for (int t = 0; t < 4; ++t)
        #pragma unroll
        for (int j = 0; j < 4; ++j)
            #pragma unroll
            for (int q = 0; q < 4; ++q) acc[t][j][q] = 0.f;

    const int KC = KROW / 32;
    const int NCHUNK = (DUAL ? 2 : 1) * KC;

    auto cpA = [&](int c, int s) {
        const __half* Ap = (DUAL && c >= KC) ? A2 : A;
        int k0 = ((DUAL && c >= KC) ? (c - KC) : c) * 32;
        if (arow < M) {
            const __half* src = Ap + (size_t)arow * KROW + k0 + a_part * 16;
            uint32_t drow = sbase + s * 16384 + a_row * 64;
            #pragma unroll
            for (int j = 0; j < 2; ++j) {
                int ch = a_part * 2 + j;
                cp_async16(drow + ((ch ^ a_sw) << 4), src + j * 8);
            }
        } else {
            char* drow = smc + s * 16384 + a_row * 64;
            #pragma unroll
            for (int j = 0; j < 2; ++j) {
                int ch = a_part * 2 + j;
                *(uint4*)(drow + ((ch ^ a_sw) << 4)) = make_uint4(0,0,0,0);
            }
        }
    };
    auto cpB = [&](int c, int s) {
        const __half* Wp = (DUAL && c >= KC) ? Wh2 : Wh;
        int cc = (DUAL && c >= KC) ? (c - KC) : c;
        const __half* src = Wp + ((size_t)cc * 2 + nb) * 4096 + tid * 16;
        uint32_t dst = sbase + s * 16384 + 8192 + tid * 32;
        cp_async16(dst,      src);
        cp_async16(dst + 16, src + 8);
    };
    auto compute_ks = [&](int s, int ks) {
        const char* a = smc + s * 16384;
        const char* b = smc + s * 16384 + 8192;
        const int lr = lane >> 2, lc = lane & 3;
        uint32_t av[4][4];
        #pragma unroll
        for (int t = 0; t < 4; ++t) {
            int m0 = warp_m * 64 + t * 16 + lr;
            int m1 = m0 + 8;
            int sw0 = (m0 >> 1) & 3, sw1 = (m1 >> 1) & 3;
            av[t][0] = *(const uint32_t*)(a + m0*64 + (((2*ks  ) ^ sw0) << 4) + lc*4);
            av[t][1] = *(const uint32_t*)(a + m1*64 + (((2*ks  ) ^ sw1) << 4) + lc*4);
            av[t][2] = *(const uint32_t*)(a + m0*64 + (((2*ks+1) ^ sw0) << 4) + lc*4);
            av[t][3] = *(const uint32_t*)(a + m1*64 + (((2*ks+1) ^ sw1) << 4) + lc*4);
        }
        #pragma unroll
        for (int j = 0; j < 4; ++j) {
            uint2 q = *(const uint2*)(b + (ks*16 + warp_n*4 + j) * 256 + lane*8);
            #pragma unroll
            for (int t = 0; t < 4; ++t)
                MMA_F16(acc[t][j], av[t], q.x, q.y);
        }
    };

    #pragma unroll
    for (int s = 0; s < 2; ++s) {
        if (s < NCHUNK) { cpA(s, s); cpB(s, s); }
        CP_COMMIT();
    }
    for (int c = 0; c < NCHUNK; ++c) {
        CP_WAIT1();
        __syncthreads();
        int sl = c + 2;
        if (sl < NCHUNK) { cpA(sl, sl % 3); cpB(sl, sl % 3); }
        CP_COMMIT();
        int s = c % 3;
        compute_ks(s, 0);
        compute_ks(s, 1);
    }

    const int row_base = bm + warp_m * 64 + (lane >> 2);
    const int col_base = nb * 128 + warp_n * 32 + (lane & 3) * 2;
    #pragma unroll
    for (int t = 0; t < 4; ++t) {
        int r0 = row_base + t * 16;
        int r1 = r0 + 8;
        float s0 = 1.f, s1 = 1.f;
        if (ROWSCALE) {
            s0 = (r0 < M) ? rowscale[r0] : 0.f;
            s1 = (r1 < M) ? rowscale[r1] : 0.f;
        }
        #pragma unroll
        for (int j = 0; j < 4; ++j) {
            int col = col_base + j * 8;
            float bb0 = __ldg(bias + col), bb1 = __ldg(bias + col + 1);
            float v00 = acc[t][j][0] + bb0 * s0;
            float v01 = acc[t][j][1] + bb1 * s0;
            float v10 = acc[t][j][2] + bb0 * s1;
            float v11 = acc[t][j][3] + bb1 * s1;
            if (RELU) {
                v00 = fmaxf(v00, 0.f); v01 = fmaxf(v01, 0.f);
                v10 = fmaxf(v10, 0.f); v11 = fmaxf(v11, 0.f);
            }
            if (OUTM == 1) {
                __half* Ch = (__half*)C;
                if (r0 < M) *(__half2*)(Ch + (size_t)r0 * 256 + col) =
                    __floats2half2_rn(v00, v01);
                if (r1 < M) *(__half2*)(Ch + (size_t)r1 * 256 + col) =
                    __floats2half2_rn(v10, v11);
            } else {
                float* Cf = (float*)C;
                if (r0 < M) *(float2*)(Cf + (size_t)r0 * 256 + col) = make_float2(v00, v01);
                if (r1 < M) *(float2*)(Cf + (size_t)r1 * 256 + col) = make_float2(v10, v11);
                if (OUTM == 2) {
                    if (r0 < M) *(__half2*)(C2 + (size_t)r0 * 256 + col) =
                        __floats2half2_rn(v00, v01);
                    if (r1 < M) *(__half2*)(C2 + (size_t)r1 * 256 + col) =
                        __floats2half2_rn(v10, v11);
                }
            }
        }
    }
}

// ---------------- fused upd2 GEMM + residual + LayerNorm (v3) -----------------
// CTA 128x256 (full rows), 512 threads = 16 warps (2M x 8N), warp tile 64x32
// (identical geometry to gemm_h). 3-stage pipeline, stage = 8KB A + 16KB B.
// u staged fp32 in smem [128][264] (135KB, reuses dead pipeline smem), then LN.
#define GEMM_LN_SMEM 135168

__global__ void __launch_bounds__(512, 1) gemm_ln_h2(
    const __half* __restrict__ A, const __half* __restrict__ Wh,
    const float* __restrict__ b2, const float* __restrict__ hin,
    const float* __restrict__ g, const float* __restrict__ b,
    float* __restrict__ ho, __half* __restrict__ hoh, int M)
{
    extern __shared__ char smc[];
    float* su = (float*)smc;
    const uint32_t sbase = smem_u32(smc);
    const int tid = threadIdx.x;
    const int wid = tid >> 5, lane = tid & 31;
    const int warp_m = wid & 1, warp_n = wid >> 1;   // 2M x 8N
    const int bm = blockIdx.x * 128;

    const int a_row = tid >> 2;          // 0..127
    const int a_part = tid & 3;          // chunk-of-16B within 64B row
    const int arow = bm + a_row;
    const int a_sw = (a_row >> 1) & 3;

    float acc[4][4][4];
    #pragma unroll
    for (int t = 0; t < 4; ++t)
        #pragma unroll
        for (int j = 0; j < 4; ++j)
            #pragma unroll
            for (int q = 0; q < 4; ++q) acc[t][j][q] = 0.f;

    auto cpA = [&](int c, int s) {
        if (arow < M) {
            const __half* src = A + (size_t)arow * 256 + c * 32 + a_part * 8;
            uint32_t drow = sbase + s * 24576 + a_row * 64;
            cp_async16(drow + ((a_part ^ a_sw) << 4), src);
        } else {
            char* drow = smc + s * 24576 + a_row * 64;
            *(uint4*)(drow + ((a_part ^ a_sw) << 4)) = make_uint4(0,0,0,0);
        }
    };
    auto cpB = [&](int c, int s) {
        const __half* src = Wh + (size_t)c * 8192 + tid * 16;
        uint32_t dst = sbase + s * 24576 + 8192 + tid * 32;
        cp_async16(dst,      src);
        cp_async16(dst + 16, src + 8);
    };
    auto compute_ks = [&](int s, int ks) {
        const char* a = smc + s * 24576;
        const char* bb = smc + s * 24576 + 8192 + (warp_n >> 2) * 8192;
        const int wn = warp_n & 3;
        const int lr = lane >> 2, lc = lane & 3;
        uint32_t av[4][4];
        #pragma unroll
        for (int t = 0; t < 4; ++t) {
            int m0 = warp_m * 64 + t * 16 + lr;
            int m1 = m0 + 8;
            int sw0 = (m0 >> 1) & 3, sw1 = (m1 >> 1) & 3;
            av[t][0] = *(const uint32_t*)(a + m0*64 + (((2*ks  ) ^ sw0) << 4) + lc*4);
            av[t][1] = *(const uint32_t*)(a + m1*64 + (((2*ks  ) ^ sw1) << 4) + lc*4);
            av[t][2] = *(const uint32_t*)(a + m0*64 + (((2*ks+1) ^ sw0) << 4) + lc*4);
            av[t][3] = *(const uint32_t*)(a + m1*64 + (((2*ks+1) ^ sw1) << 4) + lc*4);
        }
        #pragma unroll
        for (int j = 0; j < 4; ++j) {
            uint2 q = *(const uint2*)(bb + (ks*16 + wn*4 + j) * 256 + lane*8);
            #pragma unroll
            for (int t = 0; t < 4; ++t)
                MMA_F16(acc[t][j], av[t], q.x, q.y);
        }
    };

    cpA(0, 0); cpB(0, 0); CP_COMMIT();
    cpA(1, 1); cpB(1, 1); CP_COMMIT();
    for (int c = 0; c < 8; ++c) {
        CP_WAIT1();
        __syncthreads();
        int sl = c + 2;
        if (sl < 8) { cpA(sl, sl % 3); cpB(sl, sl % 3); }
        CP_COMMIT();
        int s = c % 3;
        compute_ks(s, 0);
        compute_ks(s, 1);
    }
    __syncthreads();   // pipeline smem now dead; reuse for u staging

    // ---- u = acc + b2 -> smem [128][264] fp32 ----
    {
        const int lr = lane >> 2;
        const int col_base = warp_n * 32 + (lane & 3) * 2;
        #pragma unroll
        for (int t = 0; t < 4; ++t) {
            int lr0 = warp_m * 64 + t * 16 + lr;
            int lr1 = lr0 + 8;
            #pragma unroll
            for (int j = 0; j < 4; ++j) {
                int col = col_base + j * 8;
                float bb0 = __ldg(b2 + col), bb1 = __ldg(b2 + col + 1);
                su[lr0 * 264 + col]     = acc[t][j][0] + bb0;
                su[lr0 * 264 + col + 1] = acc[t][j][1] + bb1;
                su[lr1 * 264 + col]     = acc[t][j][2] + bb0;
                su[lr1 * 264 + col + 1] = acc[t][j][3] + bb1;
            }
        }
    }
    __syncthreads();

    // ---- residual + LN: warp wid handles rows wid*8 .. wid*8+7 (128 rows) ----
    #pragma unroll 1
    for (int k = 0; k < 8; ++k) {
        int lrow = wid * 8 + k;
        int row = bm + lrow;
        if (row >= M) break;
        const float* hp = hin + (size_t)row * 256 + lane * 8;
        const float* up = su + lrow * 264 + lane * 8;
        float v[8];
        float4 h0 = *(const float4*)hp, h1 = *(const float4*)(hp + 4);
        float4 u0 = *(const float4*)up, u1 = *(const float4*)(up + 4);
        v[0]=h0.x+u0.x; v[1]=h0.y+u0.y; v[2]=h0.z+u0.z; v[3]=h0.w+u0.w;
        v[4]=h1.x+u1.x; v[5]=h1.y+u1.y; v[6]=h1.z+u1.z; v[7]=h1.w+u1.w;
        float s = 0.f;
        #pragma unroll
        for (int i = 0; i < 8; ++i) s += v[i];
        #pragma unroll
        for (int oo = 16; oo > 0; oo >>= 1) s += __shfl_xor_sync(0xffffffffu, s, oo);
        float mu = s * (1.f/256.f);
        float qq = 0.f;
        #pragma unroll
        for (int i = 0; i < 8; ++i) { float d = v[i]-mu; qq += d*d; }
        #pragma unroll
        for (int oo = 16; oo > 0; oo >>= 1) qq += __shfl_xor_sync(0xffffffffu, qq, oo);
        float rstd = rsqrtf(qq*(1.f/256.f) + 1e-5f);
        #pragma unroll
        for (int i = 0; i < 8; ++i) {
            int c = lane*8 + i;
            v[i] = (v[i]-mu)*rstd*__ldg(g+c) + __ldg(b+c);
        }
        float* op = ho + (size_t)row * 256 + lane * 8;
        *(float4*)op       = make_float4(v[0],v[1],v[2],v[3]);
        *(float4*)(op + 4) = make_float4(v[4],v[5],v[6],v[7]);
        if (hoh) {
            uint4 w;
            __half2* wp = (__half2*)&w;
            wp[0] = __floats2half2_rn(v[0], v[1]);
            wp[1] = __floats2half2_rn(v[2], v[3]);
            wp[2] = __floats2half2_rn(v[4], v[5]);
            wp[3] = __floats2half2_rn(v[6], v[7]);
            *(uint4*)(hoh + (size_t)row * 256 + lane * 8) = w;
        }
    }
}

// ---------------- f32 -> f16 elementwise (8 per thread) ----------------------
__global__ void __launch_bounds__(256) f2h_k(
    const float* __restrict__ in, __half* __restrict__ out, int n8)
{
    int i = blockIdx.x * 256 + threadIdx.x;
    if (i >= n8) return;
    float4 a = ((const float4*)in)[i*2];
    float4 b = ((const float4*)in)[i*2+1];
    uint4 o;
    __half2* op = (__half2*)&o;
    op[0] = __floats2half2_rn(a.x, a.y);
    op[1] = __floats2half2_rn(a.z, a.w);
    op[2] = __floats2half2_rn(b.x, b.y);
    op[3] = __floats2half2_rn(b.z, b.w);
    ((uint4*)out)[i] = o;
}

// ---------------- CSR build (by dst) -----------------------------------------
__global__ void __launch_bounds__(256) hist_k(
    const int* __restrict__ eidx, int* __restrict__ cnt) {
    int i = blockIdx.x * blockDim.x + threadIdx.x;
    if (i < NE) atomicAdd(&cnt[eidx[NE + i]], 1);
}

__global__ void __launch_bounds__(256) scan1_k(
    const int* __restrict__ cnt, int* __restrict__ bs) {
    __shared__ int sm[256];
    int i = blockIdx.x * 256 + threadIdx.x;
    sm[threadIdx.x] = (i < NN) ? cnt[i] : 0;
    __syncthreads();
    #pragma unroll
    for (int o = 128; o > 0; o >>= 1) {
        if (threadIdx.x < o) sm[threadIdx.x] += sm[threadIdx.x + o];
        __syncthreads();
    }
    if (threadIdx.x == 0) bs[blockIdx.x] = sm[0];
}

__global__ void __launch_bounds__(256) scan2_k(
    int* __restrict__ bs, int* __restrict__ rp) {
    __shared__ int sm[256];
    int t = threadIdx.x;
    int v = (t < NBK) ? bs[t] : 0;
    sm[t] = v;
    __syncthreads();
    #pragma unroll
    for (int o = 1; o < 256; o <<= 1) {
        int u = (t >= o) ? sm[t - o] : 0;
        __syncthreads();
        sm[t] += u;
        __syncthreads();
    }
    if (t < NBK) bs[t] = sm[t] - v;
    if (t == NBK - 1) rp[NN] = sm[t];
}

__global__ void __launch_bounds__(256) scan3_k(
    const int* __restrict__ bs, int* __restrict__ rp, int* __restrict__ cur) {
    __shared__ int sm[256];
    int i = blockIdx.x * 256 + threadIdx.x;
    int v = (i < NN) ? cur[i] : 0;
    sm[threadIdx.x] = v;
    __syncthreads();
    #pragma unroll
    for (int o = 1; o < 256; o <<= 1) {
        int u = (threadIdx.x >= o) ? sm[threadIdx.x - o] : 0;
        __syncthreads();
        sm[threadIdx.x] += u;
        __syncthreads();
    }
    if (i < NN) {
        int off = bs[blockIdx.x] + sm[threadIdx.x] - v;
        rp[i] = off;
        cur[i] = off;
    }
}

__global__ void __launch_bounds__(256) scatter_k(
    const int* __restrict__ eidx, int* __restrict__ cur, int* __restrict__ el) {
    int e = blockIdx.x * blockDim.x + threadIdx.x;
    if (e < NE) {
        int pos = atomicAdd(&cur[eidx[NE + e]], 1);
        el[pos] = eidx[e];
    }
}

// ---------------- SpMM gather: half h -> half agg (4-edge unroll) ------------
__global__ void __launch_bounds__(256) spmm_gather_k(
    const __half* __restrict__ hh, const int* __restrict__ rp,
    const int* __restrict__ el, __half* __restrict__ agg)
{
    int n = (blockIdx.x * 256 + threadIdx.x) >> 5;
    if (n >= NN) return;
    const int lane = threadIdx.x & 31;
    const int c = lane * 8;
    int s = rp[n], e = rp[n + 1];
    float a0 = 0.f, a1 = 0.f, a2 = 0.f, a3 = 0.f;
    float a4 = 0.f, a5 = 0.f, a6 = 0.f, a7 = 0.f;
    auto addrow = [&](uint4 r) {
        __half2* p = (__half2*)&r;
        float2 f0 = __half22float2(p[0]);
        float2 f1 = __half22float2(p[1]);
        float2 f2 = __half22float2(p[2]);
        float2 f3 = __half22float2(p[3]);
        a0 += f0.x; a1 += f0.y; a2 += f1.x; a3 += f1.y;
        a4 += f2.x; a5 += f2.y; a6 += f3.x; a7 += f3.y;
    };
    int i = s;
    for (; i + 3 < e; i += 4) {
        int s0 = __ldg(el + i),     s1 = __ldg(el + i + 1);
        int s2 = __ldg(el + i + 2), s3 = __ldg(el + i + 3);
        uint4 r0 = *(const uint4*)(hh + (size_t)s0 * 256 + c);
        uint4 r1 = *(const uint4*)(hh + (size_t)s1 * 256 + c);
        uint4 r2 = *(const uint4*)(hh + (size_t)s2 * 256 + c);
        uint4 r3 = *(const uint4*)(hh + (size_t)s3 * 256 + c);
        addrow(r0); addrow(r1); addrow(r2); addrow(r3);
    }
    for (; i < e; ++i) {
        uint4 r = *(const uint4*)(hh + (size_t)__ldg(el + i) * 256 + c);
        addrow(r);
    }
    uint4 o;
    __half2* op = (__half2*)&o;
    op[0] = __floats2half2_rn(a0, a1);
    op[1] = __floats2half2_rn(a2, a3);
    op[2] = __floats2half2_rn(a4, a5);
    op[3] = __floats2half2_rn(a6, a7);
    *(uint4*)(agg + (size_t)n * 256 + c) = o;
}

// ---------------- geo stage -> half xin ----------------------------------------
__global__ void __launch_bounds__(256) geo_k(
    const float* __restrict__ x,
    const float* __restrict__ geo_w, const float* __restrict__ geo_b,
    __half* __restrict__ out)
{
    __shared__ float gws[4096];
    __shared__ float gbs[32];
    for (int i = threadIdx.x; i < 4096; i += 256) gws[i] = geo_w[i];
    if (threadIdx.x < 32) gbs[threadIdx.x] = geo_b[threadIdx.x];
    __syncthreads();
    const int warp = threadIdx.x >> 5, lane = threadIdx.x & 31;
    for (int n0 = blockIdx.x * 8; n0 < NN; n0 += gridDim.x * 8) {
        int n = n0 + warp;
        if (n < NN) {
            const float* xr = x + (size_t)n * 160;
            float s = gbs[lane];
            #pragma unroll
            for (int k = 0; k < 128; ++k) s += __ldg(xr + k) * gws[k * 32 + lane];
            out[(size_t)n * 64 + lane]      = __float2half_rn(fmaxf(s, 0.f));
            out[(size_t)n * 64 + 32 + lane] = __float2half_rn(__ldg(xr + 128 + lane));
        }
    }
}

// ---------------- edge encoder + scatter (fp32, 16 edges per sync) -----------
__global__ void __launch_bounds__(256) edge_encode_k(
    const float* __restrict__ ea, const int* __restrict__ eidx,
    const float* __restrict__ w1, const float* __restrict__ b1,
    float* __restrict__ At, float* __restrict__ deg)
{
    const int tid = threadIdx.x;
    const int c0 = (tid & 63) * 4;
    const int slot = tid >> 6;
    float4 wreg[16];
    #pragma unroll
    for (int k = 0; k < 16; ++k)
        wreg[k] = *(const float4*)(w1 + k * 256 + c0);
    const float4 b1v = *(const float4*)(b1 + c0);

    __shared__ float eav[16][16];
    __shared__ int dsts[16];

    for (int base = blockIdx.x * 16; base < NE; base += gridDim.x * 16) {
        ((float*)eav)[tid] = ea[(size_t)base * 16 + tid];
        if (tid < 16) dsts[tid] = eidx[NE + base + tid];
        __syncthreads();
        #pragma unroll
        for (int g = 0; g < 4; ++g) {
            const int e = slot + g * 4;
            float4 acc = b1v;
            #pragma unroll
            for (int k = 0; k < 16; ++k) {
                float ev = eav[e][k];
                acc.x += wreg[k].x * ev;
                acc.y += wreg[k].y * ev;
                acc.z += wreg[k].z * ev;
                acc.w += wreg[k].w * ev;
            }
            acc.x = fmaxf(acc.x, 0.f); acc.y = fmaxf(acc.y, 0.f);
            acc.z = fmaxf(acc.z, 0.f); acc.w = fmaxf(acc.w, 0.f);
            int dst = dsts[e];
            redAdd4(At + (size_t)dst * 256 + c0, acc);
            if ((tid & 63) == 0) atomicAdd(deg + dst, 1.f);
        }
        __syncthreads();
    }
}

// ---------------- typed mean-pool partial sums -------------------------------
__global__ void __launch_bounds__(256) pool_k(
    const float* __restrict__ h, const int* __restrict__ batch,
    const int* __restrict__ ntype, float* __restrict__ ps, float* __restrict__ pc)
{
    __shared__ float acc[24][256];
    __shared__ float cnt[24];
    for (int i = threadIdx.x; i < 24*256; i += 256) (&acc[0][0])[i] = 0.f;
    if (threadIdx.x < 24) cnt[threadIdx.x] = 0.f;
    __syncthreads();
    int per = (NN + gridDim.x - 1) / gridDim.x;
    int start = blockIdx.x * per;
    int end = start + per; if (end > NN) end = NN;
    for (int n = start; n < end; ++n) {
        int idx = __ldg(ntype+n)*8 + __ldg(batch+n);
        acc[idx][threadIdx.x] += h[(size_t)n*256 + threadIdx.x];
        if (threadIdx.x == 0) cnt[idx] += 1.f;
    }
    __syncthreads();
    for (int i = threadIdx.x; i < 24*256; i += 256) atomicAdd(&ps[i], (&acc[0][0])[i]);
    if (threadIdx.x < 24) atomicAdd(&pc[threadIdx.x], cnt[threadIdx.x]);
}

// ---------------- small writeout: z + batch only ------------------------------
__global__ void __launch_bounds__(256) writeout_small_k(
    const float* __restrict__ ps, const float* __restrict__ pc,
    const int* __restrict__ batch, float* __restrict__ out, int out_size)
{
    const int total = 6144 + NN;
    int i = blockIdx.x * blockDim.x + threadIdx.x;
    if (i >= total) return;
    float v; int o;
    if (i < 6144) {
        int c = i & 255, kb = i >> 8, k = kb >> 3, bb = kb & 7;
        float cc = pc[kb]; if (cc < 1.f) cc = 1.f;
        v = ps[i] / cc;
        o = bb*768 + k*256 + c;
    } else {
        v = (float)batch[i - 6144];
        o = 6144 + NN*HD + (i - 6144);
    }
    if (o < out_size) out[o] = v;
}

// ---------------- launcher ----------------------------------------------------
extern "C" void kernel_launch(void* const* d_in, const int* in_sizes, int n_in,
                              void* d_out, int out_size)
{
    const float* x       = (const float*)d_in[0];
    const float* ea      = (const float*)d_in[1];
    const float* geo_w   = (const float*)d_in[2];
    const float* geo_b   = (const float*)d_in[3];
    const float* nin_w1  = (const float*)d_in[4];
    const float* nin_b1  = (const float*)d_in[5];
    const float* nin_w2  = (const float*)d_in[6];
    const float* nin_b2  = (const float*)d_in[7];
    const float* ee_w1   = (const float*)d_in[8];
    const float* ee_b1   = (const float*)d_in[9];
    const float* ee_w2   = (const float*)d_in[10];
    const float* ee_b2   = (const float*)d_in[11];
    const float* msgx    = (const float*)d_in[12];
    const float* msge    = (const float*)d_in[13];
    const float* upd_w1  = (const float*)d_in[14];
    const float* upd_b1  = (const float*)d_in[15];
    const float* upd_w2  = (const float*)d_in[16];
    const float* upd_b2  = (const float*)d_in[17];
    const float* ln_g    = (const float*)d_in[18];
    const float* ln_b    = (const float*)d_in[19];
    const int*   eidx    = (const int*)d_in[20];
    const int*   batch   = (const int*)d_in[21];
    const int*   ntype   = (const int*)d_in[22];
    float* out = (float*)d_out;

    float *h_, *d2f_, *deg_, *ps_, *pc_, *wtf_;
    __half *hh_, *d1h_, *d3h_, *aeh_, *xinh_, *wth_, *wt1h_;
    int *rp_, *cur_, *el_, *bs_;
    cudaGetSymbolAddress((void**)&h_,   g_h);
    cudaGetSymbolAddress((void**)&hh_,  g_hh);
    cudaGetSymbolAddress((void**)&d2f_, g_d2f);
    cudaGetSymbolAddress((void**)&deg_, g_deg);
    cudaGetSymbolAddress((void**)&ps_,  g_ps);
    cudaGetSymbolAddress((void**)&pc_,  g_pc);
    cudaGetSymbolAddress((void**)&wtf_, g_wtf);
    cudaGetSymbolAddress((void**)&d1h_, g_d1h);
    cudaGetSymbolAddress((void**)&d3h_, g_d3h);
    cudaGetSymbolAddress((void**)&aeh_, g_aeh);
    cudaGetSymbolAddress((void**)&xinh_, g_xinh);
    cudaGetSymbolAddress((void**)&wth_, g_wth);
    cudaGetSymbolAddress((void**)&wt1h_, g_wt1h);
    cudaGetSymbolAddress((void**)&rp_,  g_rp);
    cudaGetSymbolAddress((void**)&cur_, g_cur);
    cudaGetSymbolAddress((void**)&el_,  g_el);
    cudaGetSymbolAddress((void**)&bs_,  g_bs);

    cudaFuncSetAttribute((const void*)mm256_k,
        cudaFuncAttributeMaxDynamicSharedMemorySize, GEMM_SMEM);
    cudaFuncSetAttribute((const void*)gemm_h<64,false,true,1,false>,
        cudaFuncAttributeMaxDynamicSharedMemorySize, GEMM_H_SMEM);
    cudaFuncSetAttribute((const void*)gemm_h<256,false,false,2,false>,
        cudaFuncAttributeMaxDynamicSharedMemorySize, GEMM_H_SMEM);
    cudaFuncSetAttribute((const void*)gemm_h<256,false,false,1,true>,
        cudaFuncAttributeMaxDynamicSharedMemorySize, GEMM_H_SMEM);
    cudaFuncSetAttribute((const void*)gemm_h<256,true,true,1,false>,
        cudaFuncAttributeMaxDynamicSharedMemorySize, GEMM_H_SMEM);
    cudaFuncSetAttribute((const void*)gemm_ln_h2,
        cudaFuncAttributeMaxDynamicSharedMemorySize, GEMM_LN_SMEM);

    // --- weight precompute ----------------------------------------------------
    WPtrs wpf;
    for (int l = 0; l < 4; ++l) wpf.p[l] = upd_w1 + (size_t)l*65536;
    wfrag_k<<<dim3(16, 4), 256>>>(wpf, wtf_);

    MMPtrs mp;
    for (int l = 0; l < 4; ++l) {
        mp.a[l]     = msgx + (size_t)l*65536;
        mp.a[4 + l] = msge + (size_t)l*65536;
    }
    mm256_k<<<dim3(2, 2, 8), 256, GEMM_SMEM>>>(mp, wtf_, d2f_);

    WPtrs wph;
    wph.p[0] = nin_w2;
    for (int l = 0; l < 4; ++l) {
        wph.p[1 + l] = d2f_ + (size_t)l*65536;
        wph.p[5 + l] = d2f_ + (size_t)(4+l)*65536;
        wph.p[9 + l] = upd_w2 + (size_t)l*65536;
    }
    wph.p[13] = ee_w2;
    wfrag_h_k<<<dim3(16, 14), 256>>>(wph, wth_);
    wfrag64_h_k<<<4, 256>>>(nin_w1, wt1h_);

    // --- CSR build (by dst) -----------------------------------------------------
    cudaMemsetAsync(cur_, 0, NN*sizeof(int));
    hist_k<<<(NE+255)/256, 256>>>(eidx, cur_);
    scan1_k<<<NBK, 256>>>(cur_, bs_);
    scan2_k<<<1, 256>>>(bs_, rp_);
    scan3_k<<<NBK, 256>>>(bs_, rp_, cur_);
    scatter_k<<<(NE+255)/256, 256>>>(eidx, cur_, el_);

    dim3 gg(391, 2);

    // node encoder
    geo_k<<<625, 256>>>(x, geo_w, geo_b, xinh_);
    gemm_h<64,false,true,1,false><<<gg, 256, GEMM_H_SMEM>>>(
        xinh_, wt1h_, nullptr, nullptr, nin_b1, nullptr, d1h_, nullptr, NN);
    gemm_h<256,false,false,2,false><<<gg, 256, GEMM_H_SMEM>>>(
        d1h_, wth_ + (size_t)0*65536, nullptr, nullptr, nin_b2, nullptr,
        h_, hh_, NN);

    // edge encoder scatter (fp32) -> convert to half -> ee GEMM -> aeh
    cudaMemsetAsync(d2f_, 0, (size_t)NN*HD*sizeof(float));
    cudaMemsetAsync(deg_, 0, (size_t)NN*sizeof(float));
    edge_encode_k<<<1184, 256>>>(ea, eidx, ee_w1, ee_b1, d2f_, deg_);
    f2h_k<<<(NN*HD/8+255)/256, 256>>>(d2f_, d1h_, NN*HD/8);
    gemm_h<256,false,false,1,true><<<gg, 256, GEMM_H_SMEM>>>(
        d1h_, wth_ + (size_t)13*65536, nullptr, nullptr, ee_b2, deg_,
        aeh_, nullptr, NN);

    float* hout = out + 6144;
    for (int l = 0; l < NL; ++l) {
        spmm_gather_k<<<6250, 256>>>(hh_, rp_, el_, d1h_);
        // d3h = relu(Ah@M1 + Ae@E1 + b1)
        gemm_h<256,true,true,1,false><<<gg, 256, GEMM_H_SMEM>>>(
            d1h_, wth_ + (size_t)(1+l)*65536, aeh_, wth_ + (size_t)(5+l)*65536,
            upd_b1 + l*256, nullptr, d3h_, nullptr, NN);
        // h = LN(h + d3h@upd_w2 + b2)   [fused upd2 + residual + LN, BM=128]
        gemm_ln_h2<<<391, 512, GEMM_LN_SMEM>>>(
            d3h_, wth_ + (size_t)(9+l)*65536, upd_b2 + l*256, h_,
            ln_g + l*256, ln_b + l*256,
            (l == NL-1) ? hout : h_,
            (l == NL-1) ? nullptr : hh_, NN);
    }

    cudaMemsetAsync(ps_, 0, 24*HD*sizeof(float));
    cudaMemsetAsync(pc_, 0, 24*sizeof(float));
    pool_k<<<512, 256>>>(hout, batch, ntype, ps_, pc_);
    writeout_small_k<<<(6144+NN+255)/256, 256>>>(ps_, pc_, batch, out, out_size);
}

// round 16
// speedup vs baseline: 1.0673x; 1.0561x over previous
#include <cuda_runtime.h>
#include <cuda_fp16.h>
#include <cstdint>

#define NN 50000
#define NE 300000
#define HD 256
#define NL 4
#define NBK 196   // ceil(NN/256)

// ---------------- scratch (static device globals; no allocs allowed) -------
__device__ float  g_h  [NN*HD];    // residual stream (fp32)
__device__ __half g_hh [NN*HD];    // residual stream mirror (half, for gather)
__device__ float  g_d2f[NN*HD];    // fp32 scratch: mm256 tmp, ee scatter
__device__ __half g_d1h[NN*HD];
__device__ __half g_d3h[NN*HD];
__device__ __half g_aeh[NN*HD];
__device__ __half g_xinh[NN*64];
__device__ float  g_deg[NN];
__device__ float  g_ps[24*HD];
__device__ float  g_pc[24];
__device__ __half g_wth[14*65536]; // half frags: 0 nin_w2, 1-4 M1, 5-8 E1, 9-12 upd_w2, 13 ee_w2
__device__ __half g_wt1h[16384];   // nin_w1 (K=64) half fragments
__device__ float  g_wtf[4*65536];  // fp32 tf32 frags: upd_w1 (mm256 only)
__device__ int    g_rp[NN+1];
__device__ int    g_cur[NN];
__device__ int    g_el[NE];
__device__ int    g_bs[256];

// ---------------- helpers ------------------------------------------------
__device__ __forceinline__ float tf32r(float x) {
    float r;
    asm("cvt.rna.tf32.f32 %0, %1;" : "=f"(r) : "f"(x));
    return r;
}
__device__ __forceinline__ void redAdd4(float* p, float4 v) {
    asm volatile("red.global.add.v4.f32 [%0], {%1,%2,%3,%4};"
                 :: "l"(p), "f"(v.x), "f"(v.y), "f"(v.z), "f"(v.w) : "memory");
}
__device__ __forceinline__ uint32_t smem_u32(const void* p) {
    uint32_t a;
    asm("{ .reg .u64 t; cvta.to.shared.u64 t, %1; cvt.u32.u64 %0, t; }"
        : "=r"(a) : "l"(p));
    return a;
}
__device__ __forceinline__ void cp_async16(uint32_t sdst, const void* gsrc) {
    asm volatile("cp.async.ca.shared.global [%0], [%1], 16;"
                 :: "r"(sdst), "l"(gsrc) : "memory");
}
#define CP_COMMIT() asm volatile("cp.async.commit_group;" ::: "memory")
#define CP_WAIT1()  asm volatile("cp.async.wait_group 1;" ::: "memory")

#define MMA_TF32(c, a, b0, b1)                                               \
    asm volatile("mma.sync.aligned.m16n8k8.row.col.f32.tf32.tf32.f32 "      \
        "{%0,%1,%2,%3}, {%4,%5,%6,%7}, {%8,%9}, {%0,%1,%2,%3};"             \
        : "+f"((c)[0]), "+f"((c)[1]), "+f"((c)[2]), "+f"((c)[3])            \
        : "r"((a)[0]), "r"((a)[1]), "r"((a)[2]), "r"((a)[3]),               \
          "r"(b0), "r"(b1))

#define MMA_F16(c, a, b0, b1)                                                \
    asm volatile("mma.sync.aligned.m16n8k16.row.col.f32.f16.f16.f32 "       \
        "{%0,%1,%2,%3}, {%4,%5,%6,%7}, {%8,%9}, {%0,%1,%2,%3};"             \
        : "+f"((c)[0]), "+f"((c)[1]), "+f"((c)[2]), "+f"((c)[3])            \
        : "r"((a)[0]), "r"((a)[1]), "r"((a)[2]), "r"((a)[3]),               \
          "r"(b0), "r"(b1))

struct WPtrs { const float* p[18]; };

// ---------------- fp32 weight -> tf32 lane-major fragment blocks -------------
__global__ void __launch_bounds__(256) wfrag_k(WPtrs wp, float* __restrict__ out) {
    const float* W = wp.p[blockIdx.y];
    float* O = out + (size_t)blockIdx.y * 65536 + blockIdx.x * 4096;
    const int kc = blockIdx.x >> 1, nb = blockIdx.x & 1;
    const int nl = threadIdx.x >> 1;
    const int khalf = (threadIdx.x & 1) * 16;
    const int n = nb * 128 + nl;
    #pragma unroll
    for (int g = 0; g < 4; ++g) {
        int kk0 = khalf + g * 4;
        int k = kc * 32 + kk0;
        float vv[4];
        vv[0] = tf32r(W[(size_t)(k+0)*256 + n]);
        vv[1] = tf32r(W[(size_t)(k+1)*256 + n]);
        vv[2] = tf32r(W[(size_t)(k+2)*256 + n]);
        vv[3] = tf32r(W[(size_t)(k+3)*256 + n]);
        int base = ((kk0>>3)*8 + (nl>>4))*128 + (nl&7)*16
                 + ((((nl>>3)&1)<<1) | ((kk0>>2)&1));
        #pragma unroll
        for (int q = 0; q < 4; ++q) O[base + q*4] = vv[q];
    }
}

// ---------------- fp32 weight -> f16 m16n8k16 fragment blocks ----------------
__global__ void __launch_bounds__(256) wfrag_h_k(WPtrs wp, __half* __restrict__ out) {
    const float* W = wp.p[blockIdx.y];
    __half* O = out + (size_t)blockIdx.y * 65536 + blockIdx.x * 4096;
    const int kc = blockIdx.x >> 1, nb = blockIdx.x & 1;
    const int nl = threadIdx.x >> 1;
    const int kp = (threadIdx.x & 1);
    const int n = nb * 128 + nl;
    const int group = kp * 16 + (nl >> 3);
    const int n8 = nl & 7;
    #pragma unroll
    for (int kk = 0; kk < 16; ++kk) {
        int k = kc * 32 + kp * 16 + kk;
        __half v = __float2half_rn(W[(size_t)k * 256 + n]);
        int lane = n8 * 4 + ((kk >> 1) & 3);
        int pos = group * 128 + lane * 4 + ((kk >> 3) << 1) + (kk & 1);
        O[pos] = v;
    }
}

__global__ void __launch_bounds__(256) wfrag64_h_k(
    const float* __restrict__ W, __half* __restrict__ out) {
    __half* O = out + blockIdx.x * 4096;
    const int kc = blockIdx.x >> 1, nb = blockIdx.x & 1;
    const int nl = threadIdx.x >> 1;
    const int kp = (threadIdx.x & 1);
    const int n = nb * 128 + nl;
    const int group = kp * 16 + (nl >> 3);
    const int n8 = nl & 7;
    #pragma unroll
    for (int kk = 0; kk < 16; ++kk) {
        int k = kc * 32 + kp * 16 + kk;
        __half v = __float2half_rn(W[(size_t)k * 256 + n]);
        int lane = n8 * 4 + ((kk >> 1) & 3);
        int pos = group * 128 + lane * 4 + ((kk >> 3) << 1) + (kk & 1);
        O[pos] = v;
    }
}

// ---------------- fp32 tf32 GEMM (mm256 precompute only) --------------------
#define GEMM_SMEM 98304

struct MMPtrs { const float* a[8]; };
__global__ void __launch_bounds__(256, 2) mm256_k(
    MMPtrs mp, const float* __restrict__ wtf, float* __restrict__ tmp)
{
    extern __shared__ float smf[];
    const uint32_t sbase = smem_u32(smf);
    const float* A = mp.a[blockIdx.z];
    const float* Wf = wtf + (size_t)(blockIdx.z & 3) * 65536;
    float* C = tmp + (size_t)blockIdx.z * 65536;
    const int nb = blockIdx.y;
    const int tid = threadIdx.x;
    const int wid = tid >> 5, lane = tid & 31;
    const int warp_m = wid & 1, warp_n = wid >> 1;
    const int bm = blockIdx.x * 128;

    const int a_row = tid >> 1;
    const int a_half = tid & 1;
    const int arow = bm + a_row;
    const int a_sw = a_row & 7;

    float acc[4][4][4];
    #pragma unroll
    for (int t = 0; t < 4; ++t)
        #pragma unroll
        for (int j = 0; j < 4; ++j)
            #pragma unroll
            for (int q = 0; q < 4; ++q) acc[t][j][q] = 0.f;

    auto cpA = [&](int c, int s) {
        const float* src = A + (size_t)arow * 256 + c * 32 + a_half * 16;
        uint32_t drow = sbase + s * 32768 + a_row * 128;
        #pragma unroll
        for (int j = 0; j < 4; ++j) {
            int chunk = a_half * 4 + j;
            cp_async16(drow + ((chunk ^ a_sw) << 4), src + j * 4);
        }
    };
    auto cpB = [&](int c, int s) {
        const float* src = Wf + ((size_t)c * 2 + nb) * 4096 + tid * 16;
        uint32_t dst = sbase + s * 32768 + 16384 + tid * 64;
        #pragma unroll
        for (int i = 0; i < 4; ++i)
            cp_async16(dst + i * 16, src + i * 4);
    };
    auto compute_ks = [&](int s, int ks) {
        const float* a = smf + s * 8192;
        const float* b = smf + s * 8192 + 4096;
        const int lr = lane >> 2, lc = lane & 3;
        uint32_t av[4][4];
        float4 bq[2];
        #pragma unroll
        for (int t = 0; t < 4; ++t) {
            int m0 = warp_m * 64 + t * 16 + lr;
            #pragma unroll
            for (int i = 0; i < 4; ++i) {
                int row = m0 + (i & 1) * 8;
                int chunk = 2 * ks + (i >> 1);
                float v = a[row * 32 + ((chunk ^ lr) << 2) + lc];
                av[t][i] = __float_as_uint(tf32r(v));
            }
        }
        #pragma unroll
        for (int p = 0; p < 2; ++p)
            bq[p] = *(const float4*)&b[((ks * 8 + warp_n * 2 + p) * 32 + lane) * 4];
        #pragma unroll
        for (int t = 0; t < 4; ++t)
            #pragma unroll
            for (int p = 0; p < 2; ++p) {
                MMA_TF32(acc[t][p*2+0], av[t],
                         __float_as_uint(bq[p].x), __float_as_uint(bq[p].y));
                MMA_TF32(acc[t][p*2+1], av[t],
                         __float_as_uint(bq[p].z), __float_as_uint(bq[p].w));
            }
    };

    #pragma unroll
    for (int s = 0; s < 2; ++s) { cpA(s, s); cpB(s, s); CP_COMMIT(); }
    for (int c = 0; c < 8; ++c) {
        CP_WAIT1();
        __syncthreads();
        int sl = c + 2;
        if (sl < 8) { cpA(sl, sl % 3); cpB(sl, sl % 3); }
        CP_COMMIT();
        int s = c % 3;
        compute_ks(s, 0); compute_ks(s, 1); compute_ks(s, 2); compute_ks(s, 3);
    }
    const int row_base = bm + warp_m * 64 + (lane >> 2);
    const int col_base = nb * 128 + warp_n * 32 + (lane & 3) * 2;
    #pragma unroll
    for (int t = 0; t < 4; ++t) {
        int r0 = row_base + t * 16, r1 = r0 + 8;
        #pragma unroll
        for (int j = 0; j < 4; ++j) {
            int col = col_base + j * 8;
            *(float2*)(C + (size_t)r0 * 256 + col) = make_float2(acc[t][j][0], acc[t][j][1]);
            *(float2*)(C + (size_t)r1 * 256 + col) = make_float2(acc[t][j][2], acc[t][j][3]);
        }
    }
}

// ---------------- fp16 m16n8k16 GEMM (split-N) --------------------------------
// CTA 128x128, 8 warps (2M x 4N), warp tile 64x32. K chunks of 32, 3 stages.
// OUTM: 0=float C, 1=half C, 2=float C + half C2
#define GEMM_H_SMEM 49152

template<int KROW, bool DUAL, bool RELU, int OUTM, bool ROWSCALE>
__global__ void __launch_bounds__(256, 2) gemm_h(
    const __half* __restrict__ A,  const __half* __restrict__ Wh,
    const __half* __restrict__ A2, const __half* __restrict__ Wh2,
    const float* __restrict__ bias, const float* __restrict__ rowscale,
    void* __restrict__ C, __half* __restrict__ C2, int M)
{
    extern __shared__ char smc[];
    const uint32_t sbase = smem_u32(smc);
    const int tid = threadIdx.x;
    const int wid = tid >> 5, lane = tid & 31;
    const int warp_m = wid & 1, warp_n = wid >> 1;
    const int bm = blockIdx.x * 128;
    const int nb = blockIdx.y;

    const int a_row = tid >> 1;
    const int a_part = tid & 1;
    const int arow = bm + a_row;
    const int a_sw = (a_row >> 1) & 3;

    float acc[4][4][4];
    #pragma unroll
    for (int t = 0; t < 4; ++t)
        #pragma unroll
        for (int j = 0; j < 4; ++j)
            #pragma unroll
            for (int q = 0; q < 4; ++q) acc[t][j][q] = 0.f;

    const int KC = KROW / 32;
    const int NCHUNK = (DUAL ? 2 : 1) * KC;

    auto cpA = [&](int c, int s) {
        const __half* Ap = (DUAL && c >= KC) ? A2 : A;
        int k0 = ((DUAL && c >= KC) ? (c - KC) : c) * 32;
        if (arow < M) {
            const __half* src = Ap + (size_t)arow * KROW + k0 + a_part * 16;
            uint32_t drow = sbase + s * 16384 + a_row * 64;
            #pragma unroll
            for (int j = 0; j < 2; ++j) {
                int ch = a_part * 2 + j;
                cp_async16(drow + ((ch ^ a_sw) << 4), src + j * 8);
            }
        } else {
            char* drow = smc + s * 16384 + a_row * 64;
            #pragma unroll
            for (int j = 0; j < 2; ++j) {
                int ch = a_part * 2 + j;
                *(uint4*)(drow + ((ch ^ a_sw) << 4)) = make_uint4(0,0,0,0);
            }
        }
    };
    auto cpB = [&](int c, int s) {
        const __half* Wp = (DUAL && c >= KC) ? Wh2 : Wh;
        int cc = (DUAL && c >= KC) ? (c - KC) : c;
        const __half* src = Wp + ((size_t)cc * 2 + nb) * 4096 + tid * 16;
        uint32_t dst = sbase + s * 16384 + 8192 + tid * 32;
        cp_async16(dst,      src);
        cp_async16(dst + 16, src + 8);
    };
    auto compute_ks = [&](int s, int ks) {
        const char* a = smc + s * 16384;
        const char* b = smc + s * 16384 + 8192;
        const int lr = lane >> 2, lc = lane & 3;
        uint32_t av[4][4];
        #pragma unroll
        for (int t = 0; t < 4; ++t) {
            int m0 = warp_m * 64 + t * 16 + lr;
            int m1 = m0 + 8;
            int sw0 = (m0 >> 1) & 3, sw1 = (m1 >> 1) & 3;
            av[t][0] = *(const uint32_t*)(a + m0*64 + (((2*ks  ) ^ sw0) << 4) + lc*4);
            av[t][1] = *(const uint32_t*)(a + m1*64 + (((2*ks  ) ^ sw1) << 4) + lc*4);
            av[t][2] = *(const uint32_t*)(a + m0*64 + (((2*ks+1) ^ sw0) << 4) + lc*4);
            av[t][3] = *(const uint32_t*)(a + m1*64 + (((2*ks+1) ^ sw1) << 4) + lc*4);
        }
        #pragma unroll
        for (int j = 0; j < 4; ++j) {
            uint2 q = *(const uint2*)(b + (ks*16 + warp_n*4 + j) * 256 + lane*8);
            #pragma unroll
            for (int t = 0; t < 4; ++t)
                MMA_F16(acc[t][j], av[t], q.x, q.y);
        }
    };

    #pragma unroll
    for (int s = 0; s < 2; ++s) {
        if (s < NCHUNK) { cpA(s, s); cpB(s, s); }
        CP_COMMIT();
    }
    for (int c = 0; c < NCHUNK; ++c) {
        CP_WAIT1();
        __syncthreads();
        int sl = c + 2;
        if (sl < NCHUNK) { cpA(sl, sl % 3); cpB(sl, sl % 3); }
        CP_COMMIT();
        int s = c % 3;
        compute_ks(s, 0);
        compute_ks(s, 1);
    }

    const int row_base = bm + warp_m * 64 + (lane >> 2);
    const int col_base = nb * 128 + warp_n * 32 + (lane & 3) * 2;
    #pragma unroll
    for (int t = 0; t < 4; ++t) {
        int r0 = row_base + t * 16;
        int r1 = r0 + 8;
        float s0 = 1.f, s1 = 1.f;
        if (ROWSCALE) {
            s0 = (r0 < M) ? rowscale[r0] : 0.f;
            s1 = (r1 < M) ? rowscale[r1] : 0.f;
        }
        #pragma unroll
        for (int j = 0; j < 4; ++j) {
            int col = col_base + j * 8;
            float bb0 = __ldg(bias + col), bb1 = __ldg(bias + col + 1);
            float v00 = acc[t][j][0] + bb0 * s0;
            float v01 = acc[t][j][1] + bb1 * s0;
            float v10 = acc[t][j][2] + bb0 * s1;
            float v11 = acc[t][j][3] + bb1 * s1;
            if (RELU) {
                v00 = fmaxf(v00, 0.f); v01 = fmaxf(v01, 0.f);
                v10 = fmaxf(v10, 0.f); v11 = fmaxf(v11, 0.f);
            }
            if (OUTM == 1) {
                __half* Ch = (__half*)C;
                if (r0 < M) *(__half2*)(Ch + (size_t)r0 * 256 + col) =
                    __floats2half2_rn(v00, v01);
                if (r1 < M) *(__half2*)(Ch + (size_t)r1 * 256 + col) =
                    __floats2half2_rn(v10, v11);
            } else {
                float* Cf = (float*)C;
                if (r0 < M) *(float2*)(Cf + (size_t)r0 * 256 + col) = make_float2(v00, v01);
                if (r1 < M) *(float2*)(Cf + (size_t)r1 * 256 + col) = make_float2(v10, v11);
                if (OUTM == 2) {
                    if (r0 < M) *(__half2*)(C2 + (size_t)r0 * 256 + col) =
                        __floats2half2_rn(v00, v01);
                    if (r1 < M) *(__half2*)(C2 + (size_t)r1 * 256 + col) =
                        __floats2half2_rn(v10, v11);
                }
            }
        }
    }
}

// ---------------- f32 -> f16 elementwise (8 per thread) ----------------------
__global__ void __launch_bounds__(256) f2h_k(
    const float* __restrict__ in, __half* __restrict__ out, int n8)
{
    int i = blockIdx.x * 256 + threadIdx.x;
    if (i >= n8) return;
    float4 a = ((const float4*)in)[i*2];
    float4 b = ((const float4*)in)[i*2+1];
    uint4 o;
    __half2* op = (__half2*)&o;
    op[0] = __floats2half2_rn(a.x, a.y);
    op[1] = __floats2half2_rn(a.z, a.w);
    op[2] = __floats2half2_rn(b.x, b.y);
    op[3] = __floats2half2_rn(b.z, b.w);
    ((uint4*)out)[i] = o;
}

// ---------------- CSR build (by dst) -----------------------------------------
__global__ void __launch_bounds__(256) hist_k(
    const int* __restrict__ eidx, int* __restrict__ cnt) {
    int i = blockIdx.x * blockDim.x + threadIdx.x;
    if (i < NE) atomicAdd(&cnt[eidx[NE + i]], 1);
}

__global__ void __launch_bounds__(256) scan1_k(
    const int* __restrict__ cnt, int* __restrict__ bs) {
    __shared__ int sm[256];
    int i = blockIdx.x * 256 + threadIdx.x;
    sm[threadIdx.x] = (i < NN) ? cnt[i] : 0;
    __syncthreads();
    #pragma unroll
    for (int o = 128; o > 0; o >>= 1) {
        if (threadIdx.x < o) sm[threadIdx.x] += sm[threadIdx.x + o];
        __syncthreads();
    }
    if (threadIdx.x == 0) bs[blockIdx.x] = sm[0];
}

__global__ void __launch_bounds__(256) scan2_k(
    int* __restrict__ bs, int* __restrict__ rp) {
    __shared__ int sm[256];
    int t = threadIdx.x;
    int v = (t < NBK) ? bs[t] : 0;
    sm[t] = v;
    __syncthreads();
    #pragma unroll
    for (int o = 1; o < 256; o <<= 1) {
        int u = (t >= o) ? sm[t - o] : 0;
        __syncthreads();
        sm[t] += u;
        __syncthreads();
    }
    if (t < NBK) bs[t] = sm[t] - v;
    if (t == NBK - 1) rp[NN] = sm[t];
}

__global__ void __launch_bounds__(256) scan3_k(
    const int* __restrict__ bs, int* __restrict__ rp, int* __restrict__ cur) {
    __shared__ int sm[256];
    int i = blockIdx.x * 256 + threadIdx.x;
    int v = (i < NN) ? cur[i] : 0;
    sm[threadIdx.x] = v;
    __syncthreads();
    #pragma unroll
    for (int o = 1; o < 256; o <<= 1) {
        int u = (threadIdx.x >= o) ? sm[threadIdx.x - o] : 0;
        __syncthreads();
        sm[threadIdx.x] += u;
        __syncthreads();
    }
    if (i < NN) {
        int off = bs[blockIdx.x] + sm[threadIdx.x] - v;
        rp[i] = off;
        cur[i] = off;
    }
}

__global__ void __launch_bounds__(256) scatter_k(
    const int* __restrict__ eidx, int* __restrict__ cur, int* __restrict__ el) {
    int e = blockIdx.x * blockDim.x + threadIdx.x;
    if (e < NE) {
        int pos = atomicAdd(&cur[eidx[NE + e]], 1);
        el[pos] = eidx[e];
    }
}

// ---------------- SpMM gather: half h -> half agg (4-edge unroll) ------------
__global__ void __launch_bounds__(256) spmm_gather_k(
    const __half* __restrict__ hh, const int* __restrict__ rp,
    const int* __restrict__ el, __half* __restrict__ agg)
{
    int n = (blockIdx.x * 256 + threadIdx.x) >> 5;
    if (n >= NN) return;
    const int lane = threadIdx.x & 31;
    const int c = lane * 8;
    int s = rp[n], e = rp[n + 1];
    float a0 = 0.f, a1 = 0.f, a2 = 0.f, a3 = 0.f;
    float a4 = 0.f, a5 = 0.f, a6 = 0.f, a7 = 0.f;
    auto addrow = [&](uint4 r) {
        __half2* p = (__half2*)&r;
        float2 f0 = __half22float2(p[0]);
        float2 f1 = __half22float2(p[1]);
        float2 f2 = __half22float2(p[2]);
        float2 f3 = __half22float2(p[3]);
        a0 += f0.x; a1 += f0.y; a2 += f1.x; a3 += f1.y;
        a4 += f2.x; a5 += f2.y; a6 += f3.x; a7 += f3.y;
    };
    int i = s;
    for (; i + 3 < e; i += 4) {
        int s0 = __ldg(el + i),     s1 = __ldg(el + i + 1);
        int s2 = __ldg(el + i + 2), s3 = __ldg(el + i + 3);
        uint4 r0 = *(const uint4*)(hh + (size_t)s0 * 256 + c);
        uint4 r1 = *(const uint4*)(hh + (size_t)s1 * 256 + c);
        uint4 r2 = *(const uint4*)(hh + (size_t)s2 * 256 + c);
        uint4 r3 = *(const uint4*)(hh + (size_t)s3 * 256 + c);
        addrow(r0); addrow(r1); addrow(r2); addrow(r3);
    }
    for (; i < e; ++i) {
        uint4 r = *(const uint4*)(hh + (size_t)__ldg(el + i) * 256 + c);
        addrow(r);
    }
    uint4 o;
    __half2* op = (__half2*)&o;
    op[0] = __floats2half2_rn(a0, a1);
    op[1] = __floats2half2_rn(a2, a3);
    op[2] = __floats2half2_rn(a4, a5);
    op[3] = __floats2half2_rn(a6, a7);
    *(uint4*)(agg + (size_t)n * 256 + c) = o;
}

// ---------------- geo stage -> half xin ----------------------------------------
__global__ void __launch_bounds__(256) geo_k(
    const float* __restrict__ x,
    const float* __restrict__ geo_w, const float* __restrict__ geo_b,
    __half* __restrict__ out)
{
    __shared__ float gws[4096];
    __shared__ float gbs[32];
    for (int i = threadIdx.x; i < 4096; i += 256) gws[i] = geo_w[i];
    if (threadIdx.x < 32) gbs[threadIdx.x] = geo_b[threadIdx.x];
    __syncthreads();
    const int warp = threadIdx.x >> 5, lane = threadIdx.x & 31;
    for (int n0 = blockIdx.x * 8; n0 < NN; n0 += gridDim.x * 8) {
        int n = n0 + warp;
        if (n < NN) {
            const float* xr = x + (size_t)n * 160;
            float s = gbs[lane];
            #pragma unroll
            for (int k = 0; k < 128; ++k) s += __ldg(xr + k) * gws[k * 32 + lane];
            out[(size_t)n * 64 + lane]      = __float2half_rn(fmaxf(s, 0.f));
            out[(size_t)n * 64 + 32 + lane] = __float2half_rn(__ldg(xr + 128 + lane));
        }
    }
}

// ---------------- edge encoder + scatter (fp32, 16 edges per sync) -----------
__global__ void __launch_bounds__(256) edge_encode_k(
    const float* __restrict__ ea, const int* __restrict__ eidx,
    const float* __restrict__ w1, const float* __restrict__ b1,
    float* __restrict__ At, float* __restrict__ deg)
{
    const int tid = threadIdx.x;
    const int c0 = (tid & 63) * 4;
    const int slot = tid >> 6;
    float4 wreg[16];
    #pragma unroll
    for (int k = 0; k < 16; ++k)
        wreg[k] = *(const float4*)(w1 + k * 256 + c0);
    const float4 b1v = *(const float4*)(b1 + c0);

    __shared__ float eav[16][16];
    __shared__ int dsts[16];

    for (int base = blockIdx.x * 16; base < NE; base += gridDim.x * 16) {
        ((float*)eav)[tid] = ea[(size_t)base * 16 + tid];
        if (tid < 16) dsts[tid] = eidx[NE + base + tid];
        __syncthreads();
        #pragma unroll
        for (int g = 0; g < 4; ++g) {
            const int e = slot + g * 4;
            float4 acc = b1v;
            #pragma unroll
            for (int k = 0; k < 16; ++k) {
                float ev = eav[e][k];
                acc.x += wreg[k].x * ev;
                acc.y += wreg[k].y * ev;
                acc.z += wreg[k].z * ev;
                acc.w += wreg[k].w * ev;
            }
            acc.x = fmaxf(acc.x, 0.f); acc.y = fmaxf(acc.y, 0.f);
            acc.z = fmaxf(acc.z, 0.f); acc.w = fmaxf(acc.w, 0.f);
            int dst = dsts[e];
            redAdd4(At + (size_t)dst * 256 + c0, acc);
            if ((tid & 63) == 0) atomicAdd(deg + dst, 1.f);
        }
        __syncthreads();
    }
}

// ---------------- residual + layernorm (fp32 h, half u) ----------------------
__global__ void __launch_bounds__(256) ln_k(
    const float* h, const __half* __restrict__ u,
    const float* __restrict__ g, const float* __restrict__ b,
    float* o, __half* oh)
{
    int gw = (blockIdx.x*blockDim.x + threadIdx.x) >> 5;
    int lane = threadIdx.x & 31;
    int nw = (gridDim.x*blockDim.x) >> 5;
    for (int n = gw; n < NN; n += nw) {
        const float* hp = h + (size_t)n*256;
        float v[8];
        float4 h0 = *(const float4*)(hp + lane*8), h1 = *(const float4*)(hp + lane*8 + 4);
        uint4 ur = *(const uint4*)(u + (size_t)n*256 + lane*8);
        __half2* up = (__half2*)&ur;
        float2 u0 = __half22float2(up[0]);
        float2 u1 = __half22float2(up[1]);
        float2 u2 = __half22float2(up[2]);
        float2 u3 = __half22float2(up[3]);
        v[0]=h0.x+u0.x; v[1]=h0.y+u0.y; v[2]=h0.z+u1.x; v[3]=h0.w+u1.y;
        v[4]=h1.x+u2.x; v[5]=h1.y+u2.y; v[6]=h1.z+u3.x; v[7]=h1.w+u3.y;
        float s = 0.f;
        #pragma unroll
        for (int i = 0; i < 8; ++i) s += v[i];
        #pragma unroll
        for (int oo = 16; oo > 0; oo >>= 1) s += __shfl_xor_sync(0xffffffffu, s, oo);
        float mu = s * (1.f/256.f);
        float qq = 0.f;
        #pragma unroll
        for (int i = 0; i < 8; ++i) { float d = v[i]-mu; qq += d*d; }
        #pragma unroll
        for (int oo = 16; oo > 0; oo >>= 1) qq += __shfl_xor_sync(0xffffffffu, qq, oo);
        float rstd = rsqrtf(qq*(1.f/256.f) + 1e-5f);
        #pragma unroll
        for (int i = 0; i < 8; ++i) {
            int c = lane*8 + i;
            v[i] = (v[i]-mu)*rstd*__ldg(g+c) + __ldg(b+c);
        }
        float* op = o + (size_t)n*256;
        *(float4*)(op + lane*8)     = make_float4(v[0],v[1],v[2],v[3]);
        *(float4*)(op + lane*8 + 4) = make_float4(v[4],v[5],v[6],v[7]);
        if (oh) {
            uint4 w;
            __half2* wp = (__half2*)&w;
            wp[0] = __floats2half2_rn(v[0], v[1]);
            wp[1] = __floats2half2_rn(v[2], v[3]);
            wp[2] = __floats2half2_rn(v[4], v[5]);
            wp[3] = __floats2half2_rn(v[6], v[7]);
            *(uint4*)(oh + (size_t)n*256 + lane*8) = w;
        }
    }
}

// ---------------- typed mean-pool partial sums -------------------------------
__global__ void __launch_bounds__(256) pool_k(
    const float* __restrict__ h, const int* __restrict__ batch,
    const int* __restrict__ ntype, float* __restrict__ ps, float* __restrict__ pc)
{
    __shared__ float acc[24][256];
    __shared__ float cnt[24];
    for (int i = threadIdx.x; i < 24*256; i += 256) (&acc[0][0])[i] = 0.f;
    if (threadIdx.x < 24) cnt[threadIdx.x] = 0.f;
    __syncthreads();
    int per = (NN + gridDim.x - 1) / gridDim.x;
    int start = blockIdx.x * per;
    int end = start + per; if (end > NN) end = NN;
    for (int n = start; n < end; ++n) {
        int idx = __ldg(ntype+n)*8 + __ldg(batch+n);
        acc[idx][threadIdx.x] += h[(size_t)n*256 + threadIdx.x];
        if (threadIdx.x == 0) cnt[idx] += 1.f;
    }
    __syncthreads();
    for (int i = threadIdx.x; i < 24*256; i += 256) atomicAdd(&ps[i], (&acc[0][0])[i]);
    if (threadIdx.x < 24) atomicAdd(&pc[threadIdx.x], cnt[threadIdx.x]);
}

// ---------------- small writeout: z + batch only ------------------------------
__global__ void __launch_bounds__(256) writeout_small_k(
    const float* __restrict__ ps, const float* __restrict__ pc,
    const int* __restrict__ batch, float* __restrict__ out, int out_size)
{
    const int total = 6144 + NN;
    int i = blockIdx.x * blockDim.x + threadIdx.x;
    if (i >= total) return;
    float v; int o;
    if (i < 6144) {
        int c = i & 255, kb = i >> 8, k = kb >> 3, bb = kb & 7;
        float cc = pc[kb]; if (cc < 1.f) cc = 1.f;
        v = ps[i] / cc;
        o = bb*768 + k*256 + c;
    } else {
        v = (float)batch[i - 6144];
        o = 6144 + NN*HD + (i - 6144);
    }
    if (o < out_size) out[o] = v;
}

// ---------------- launcher ----------------------------------------------------
extern "C" void kernel_launch(void* const* d_in, const int* in_sizes, int n_in,
                              void* d_out, int out_size)
{
    const float* x       = (const float*)d_in[0];
    const float* ea      = (const float*)d_in[1];
    const float* geo_w   = (const float*)d_in[2];
    const float* geo_b   = (const float*)d_in[3];
    const float* nin_w1  = (const float*)d_in[4];
    const float* nin_b1  = (const float*)d_in[5];
    const float* nin_w2  = (const float*)d_in[6];
    const float* nin_b2  = (const float*)d_in[7];
    const float* ee_w1   = (const float*)d_in[8];
    const float* ee_b1   = (const float*)d_in[9];
    const float* ee_w2   = (const float*)d_in[10];
    const float* ee_b2   = (const float*)d_in[11];
    const float* msgx    = (const float*)d_in[12];
    const float* msge    = (const float*)d_in[13];
    const float* upd_w1  = (const float*)d_in[14];
    const float* upd_b1  = (const float*)d_in[15];
    const float* upd_w2  = (const float*)d_in[16];
    const float* upd_b2  = (const float*)d_in[17];
    const float* ln_g    = (const float*)d_in[18];
    const float* ln_b    = (const float*)d_in[19];
    const int*   eidx    = (const int*)d_in[20];
    const int*   batch   = (const int*)d_in[21];
    const int*   ntype   = (const int*)d_in[22];
    float* out = (float*)d_out;

    float *h_, *d2f_, *deg_, *ps_, *pc_, *wtf_;
    __half *hh_, *d1h_, *d3h_, *aeh_, *xinh_, *wth_, *wt1h_;
    int *rp_, *cur_, *el_, *bs_;
    cudaGetSymbolAddress((void**)&h_,   g_h);
    cudaGetSymbolAddress((void**)&hh_,  g_hh);
    cudaGetSymbolAddress((void**)&d2f_, g_d2f);
    cudaGetSymbolAddress((void**)&deg_, g_deg);
    cudaGetSymbolAddress((void**)&ps_,  g_ps);
    cudaGetSymbolAddress((void**)&pc_,  g_pc);
    cudaGetSymbolAddress((void**)&wtf_, g_wtf);
    cudaGetSymbolAddress((void**)&d1h_, g_d1h);
    cudaGetSymbolAddress((void**)&d3h_, g_d3h);
    cudaGetSymbolAddress((void**)&aeh_, g_aeh);
    cudaGetSymbolAddress((void**)&xinh_, g_xinh);
    cudaGetSymbolAddress((void**)&wth_, g_wth);
    cudaGetSymbolAddress((void**)&wt1h_, g_wt1h);
    cudaGetSymbolAddress((void**)&rp_,  g_rp);
    cudaGetSymbolAddress((void**)&cur_, g_cur);
    cudaGetSymbolAddress((void**)&el_,  g_el);
    cudaGetSymbolAddress((void**)&bs_,  g_bs);

    cudaFuncSetAttribute((const void*)mm256_k,
        cudaFuncAttributeMaxDynamicSharedMemorySize, GEMM_SMEM);
    cudaFuncSetAttribute((const void*)gemm_h<64,false,true,1,false>,
        cudaFuncAttributeMaxDynamicSharedMemorySize, GEMM_H_SMEM);
    cudaFuncSetAttribute((const void*)gemm_h<256,false,false,2,false>,
        cudaFuncAttributeMaxDynamicSharedMemorySize, GEMM_H_SMEM);
    cudaFuncSetAttribute((const void*)gemm_h<256,false,false,1,true>,
        cudaFuncAttributeMaxDynamicSharedMemorySize, GEMM_H_SMEM);
    cudaFuncSetAttribute((const void*)gemm_h<256,true,true,1,false>,
        cudaFuncAttributeMaxDynamicSharedMemorySize, GEMM_H_SMEM);
    cudaFuncSetAttribute((const void*)gemm_h<256,false,false,1,false>,
        cudaFuncAttributeMaxDynamicSharedMemorySize, GEMM_H_SMEM);

    // --- weight precompute ----------------------------------------------------
    WPtrs wpf;
    for (int l = 0; l < 4; ++l) wpf.p[l] = upd_w1 + (size_t)l*65536;
    wfrag_k<<<dim3(16, 4), 256>>>(wpf, wtf_);

    MMPtrs mp;
    for (int l = 0; l < 4; ++l) {
        mp.a[l]     = msgx + (size_t)l*65536;
        mp.a[4 + l] = msge + (size_t)l*65536;
    }
    mm256_k<<<dim3(2, 2, 8), 256, GEMM_SMEM>>>(mp, wtf_, d2f_);

    WPtrs wph;
    wph.p[0] = nin_w2;
    for (int l = 0; l < 4; ++l) {
        wph.p[1 + l] = d2f_ + (size_t)l*65536;
        wph.p[5 + l] = d2f_ + (size_t)(4+l)*65536;
        wph.p[9 + l] = upd_w2 + (size_t)l*65536;
    }
    wph.p[13] = ee_w2;
    wfrag_h_k<<<dim3(16, 14), 256>>>(wph, wth_);
    wfrag64_h_k<<<4, 256>>>(nin_w1, wt1h_);

    // --- CSR build (by dst) -----------------------------------------------------
    cudaMemsetAsync(cur_, 0, NN*sizeof(int));
    hist_k<<<(NE+255)/256, 256>>>(eidx, cur_);
    scan1_k<<<NBK, 256>>>(cur_, bs_);
    scan2_k<<<1, 256>>>(bs_, rp_);
    scan3_k<<<NBK, 256>>>(bs_, rp_, cur_);
    scatter_k<<<(NE+255)/256, 256>>>(eidx, cur_, el_);

    dim3 gg(391, 2);

    // node encoder
    geo_k<<<625, 256>>>(x, geo_w, geo_b, xinh_);
    gemm_h<64,false,true,1,false><<<gg, 256, GEMM_H_SMEM>>>(
        xinh_, wt1h_, nullptr, nullptr, nin_b1, nullptr, d1h_, nullptr, NN);
    gemm_h<256,false,false,2,false><<<gg, 256, GEMM_H_SMEM>>>(
        d1h_, wth_ + (size_t)0*65536, nullptr, nullptr, nin_b2, nullptr,
        h_, hh_, NN);

    // edge encoder scatter (fp32) -> convert to half -> ee GEMM -> aeh
    cudaMemsetAsync(d2f_, 0, (size_t)NN*HD*sizeof(float));
    cudaMemsetAsync(deg_, 0, (size_t)NN*sizeof(float));
    edge_encode_k<<<1184, 256>>>(ea, eidx, ee_w1, ee_b1, d2f_, deg_);
    f2h_k<<<(NN*HD/8+255)/256, 256>>>(d2f_, d1h_, NN*HD/8);
    gemm_h<256,false,false,1,true><<<gg, 256, GEMM_H_SMEM>>>(
        d1h_, wth_ + (size_t)13*65536, nullptr, nullptr, ee_b2, deg_,
        aeh_, nullptr, NN);

    float* hout = out + 6144;
    for (int l = 0; l < NL; ++l) {
        spmm_gather_k<<<6250, 256>>>(hh_, rp_, el_, d1h_);
        // d3h = relu(Ah@M1 + Ae@E1 + b1)
        gemm_h<256,true,true,1,false><<<gg, 256, GEMM_H_SMEM>>>(
            d1h_, wth_ + (size_t)(1+l)*65536, aeh_, wth_ + (size_t)(5+l)*65536,
            upd_b1 + l*256, nullptr, d3h_, nullptr, NN);
        // u = d3h@upd_w2 + b2 (half out, reuses d1h — dead after dual GEMM)
        gemm_h<256,false,false,1,false><<<gg, 256, GEMM_H_SMEM>>>(
            d3h_, wth_ + (size_t)(9+l)*65536, nullptr, nullptr,
            upd_b2 + l*256, nullptr, d1h_, nullptr, NN);
        // h = LN(h + u); layers 0-2 also write half mirror
        ln_k<<<784, 256>>>(h_, d1h_, ln_g + l*256, ln_b + l*256,
                           (l == NL-1) ? hout : h_,
                           (l == NL-1) ? nullptr : hh_);
    }

    cudaMemsetAsync(ps_, 0, 24*HD*sizeof(float));
    cudaMemsetAsync(pc_, 0, 24*sizeof(float));
    pool_k<<<512, 256>>>(hout, batch, ntype, ps_, pc_);
    writeout_small_k<<<(6144+NN+255)/256, 256>>>(ps_, pc_, batch, out, out_size);
}

// round 17
// speedup vs baseline: 1.0770x; 1.0090x over previous
#include <cuda_runtime.h>
#include <cuda_fp16.h>
#include <cstdint>

#define NN 50000
#define NE 300000
#define HD 256
#define NL 4
#define NBK 196   // ceil(NN/256)

// ---------------- scratch (static device globals; no allocs allowed) -------
__device__ float  g_h  [NN*HD];    // residual stream (fp32)
__device__ __half g_hh [NN*HD];    // residual stream mirror (half, for gather)
__device__ float  g_d2f[NN*HD];    // fp32 scratch: mm256 tmp, ee scatter
__device__ __half g_d1h[NN*HD];
__device__ __half g_d3h[NN*HD];
__device__ __half g_aeh[NN*HD];
__device__ __half g_xinh[NN*64];
__device__ float  g_deg[NN];
__device__ float  g_ps[24*HD];
__device__ float  g_pc[24];
__device__ __half g_wth[18*65536]; // half frags: 0 nin_w2, 1-4 M1, 5-8 E1,
                                   // 9-12 upd_w2, 13 ee_w2, 14-17 upd_w1 (precompute)
__device__ __half g_wt1h[16384];   // nin_w1 (K=64) half fragments
__device__ int    g_rp[NN+1];
__device__ int    g_cur[NN];
__device__ int    g_el[NE];
__device__ int    g_bs[256];

// ---------------- helpers ------------------------------------------------
__device__ __forceinline__ void redAdd4(float* p, float4 v) {
    asm volatile("red.global.add.v4.f32 [%0], {%1,%2,%3,%4};"
                 :: "l"(p), "f"(v.x), "f"(v.y), "f"(v.z), "f"(v.w) : "memory");
}
__device__ __forceinline__ uint32_t smem_u32(const void* p) {
    uint32_t a;
    asm("{ .reg .u64 t; cvta.to.shared.u64 t, %1; cvt.u32.u64 %0, t; }"
        : "=r"(a) : "l"(p));
    return a;
}
__device__ __forceinline__ void cp_async16(uint32_t sdst, const void* gsrc) {
    asm volatile("cp.async.ca.shared.global [%0], [%1], 16;"
                 :: "r"(sdst), "l"(gsrc) : "memory");
}
#define CP_COMMIT() asm volatile("cp.async.commit_group;" ::: "memory")
#define CP_WAIT1()  asm volatile("cp.async.wait_group 1;" ::: "memory")

#define MMA_F16(c, a, b0, b1)                                                \
    asm volatile("mma.sync.aligned.m16n8k16.row.col.f32.f16.f16.f32 "       \
        "{%0,%1,%2,%3}, {%4,%5,%6,%7}, {%8,%9}, {%0,%1,%2,%3};"             \
        : "+f"((c)[0]), "+f"((c)[1]), "+f"((c)[2]), "+f"((c)[3])            \
        : "r"((a)[0]), "r"((a)[1]), "r"((a)[2]), "r"((a)[3]),               \
          "r"(b0), "r"(b1))

struct WPtrs { const float* p[18]; };

// ---------------- fp32 weight -> f16 m16n8k16 fragment blocks ----------------
__global__ void __launch_bounds__(256) wfrag_h_k(WPtrs wp, __half* __restrict__ out) {
    const float* W = wp.p[blockIdx.y];
    __half* O = out + (size_t)blockIdx.y * 65536 + blockIdx.x * 4096;
    const int kc = blockIdx.x >> 1, nb = blockIdx.x & 1;
    const int nl = threadIdx.x >> 1;
    const int kp = (threadIdx.x & 1);
    const int n = nb * 128 + nl;
    const int group = kp * 16 + (nl >> 3);
    const int n8 = nl & 7;
    #pragma unroll
    for (int kk = 0; kk < 16; ++kk) {
        int k = kc * 32 + kp * 16 + kk;
        __half v = __float2half_rn(W[(size_t)k * 256 + n]);
        int lane = n8 * 4 + ((kk >> 1) & 3);
        int pos = group * 128 + lane * 4 + ((kk >> 3) << 1) + (kk & 1);
        O[pos] = v;
    }
}

__global__ void __launch_bounds__(256) wfrag64_h_k(
    const float* __restrict__ W, __half* __restrict__ out) {
    __half* O = out + blockIdx.x * 4096;
    const int kc = blockIdx.x >> 1, nb = blockIdx.x & 1;
    const int nl = threadIdx.x >> 1;
    const int kp = (threadIdx.x & 1);
    const int n = nb * 128 + nl;
    const int group = kp * 16 + (nl >> 3);
    const int n8 = nl & 7;
    #pragma unroll
    for (int kk = 0; kk < 16; ++kk) {
        int k = kc * 32 + kp * 16 + kk;
        __half v = __float2half_rn(W[(size_t)k * 256 + n]);
        int lane = n8 * 4 + ((kk >> 1) & 3);
        int pos = group * 128 + lane * 4 + ((kk >> 3) << 1) + (kk & 1);
        O[pos] = v;
    }
}

// ---------------- fp16 m16n8k16 GEMM (split-N) --------------------------------
// CTA 128x128, 8 warps (2M x 4N), warp tile 64x32. K chunks of 32, 3 stages.
// OUTM: 0=float C, 1=half C, 2=float C + half C2
#define GEMM_H_SMEM 49152

template<int KROW, bool DUAL, bool RELU, int OUTM, bool ROWSCALE>
__global__ void __launch_bounds__(256, 2) gemm_h(
    const __half* __restrict__ A,  const __half* __restrict__ Wh,
    const __half* __restrict__ A2, const __half* __restrict__ Wh2,
    const float* __restrict__ bias, const float* __restrict__ rowscale,
    void* __restrict__ C, __half* __restrict__ C2, int M)
{
    extern __shared__ char smc[];
    const uint32_t sbase = smem_u32(smc);
    const int tid = threadIdx.x;
    const int wid = tid >> 5, lane = tid & 31;
    const int warp_m = wid & 1, warp_n = wid >> 1;
    const int bm = blockIdx.x * 128;
    const int nb = blockIdx.y;

    const int a_row = tid >> 1;
    const int a_part = tid & 1;
    const int arow = bm + a_row;
    const int a_sw = (a_row >> 1) & 3;

    float acc[4][4][4];
    #pragma unroll
    for (int t = 0; t < 4; ++t)
        #pragma unroll
        for (int j = 0; j < 4; ++j)
            #pragma unroll
            for (int q = 0; q < 4; ++q) acc[t][j][q] = 0.f;

    const int KC = KROW / 32;
    const int NCHUNK = (DUAL ? 2 : 1) * KC;

    auto cpA = [&](int c, int s) {
        const __half* Ap = (DUAL && c >= KC) ? A2 : A;
        int k0 = ((DUAL && c >= KC) ? (c - KC) : c) * 32;
        if (arow < M) {
            const __half* src = Ap + (size_t)arow * KROW + k0 + a_part * 16;
            uint32_t drow = sbase + s * 16384 + a_row * 64;
            #pragma unroll
            for (int j = 0; j < 2; ++j) {
                int ch = a_part * 2 + j;
                cp_async16(drow + ((ch ^ a_sw) << 4), src + j * 8);
            }
        } else {
            char* drow = smc + s * 16384 + a_row * 64;
            #pragma unroll
            for (int j = 0; j < 2; ++j) {
                int ch = a_part * 2 + j;
                *(uint4*)(drow + ((ch ^ a_sw) << 4)) = make_uint4(0,0,0,0);
            }
        }
    };
    auto cpB = [&](int c, int s) {
        const __half* Wp = (DUAL && c >= KC) ? Wh2 : Wh;
        int cc = (DUAL && c >= KC) ? (c - KC) : c;
        const __half* src = Wp + ((size_t)cc * 2 + nb) * 4096 + tid * 16;
        uint32_t dst = sbase + s * 16384 + 8192 + tid * 32;
        cp_async16(dst,      src);
        cp_async16(dst + 16, src + 8);
    };
    auto compute_ks = [&](int s, int ks) {
        const char* a = smc + s * 16384;
        const char* b = smc + s * 16384 + 8192;
        const int lr = lane >> 2, lc = lane & 3;
        uint32_t av[4][4];
        #pragma unroll
        for (int t = 0; t < 4; ++t) {
            int m0 = warp_m * 64 + t * 16 + lr;
            int m1 = m0 + 8;
            int sw0 = (m0 >> 1) & 3, sw1 = (m1 >> 1) & 3;
            av[t][0] = *(const uint32_t*)(a + m0*64 + (((2*ks  ) ^ sw0) << 4) + lc*4);
            av[t][1] = *(const uint32_t*)(a + m1*64 + (((2*ks  ) ^ sw1) << 4) + lc*4);
            av[t][2] = *(const uint32_t*)(a + m0*64 + (((2*ks+1) ^ sw0) << 4) + lc*4);
            av[t][3] = *(const uint32_t*)(a + m1*64 + (((2*ks+1) ^ sw1) << 4) + lc*4);
        }
        #pragma unroll
        for (int j = 0; j < 4; ++j) {
            uint2 q = *(const uint2*)(b + (ks*16 + warp_n*4 + j) * 256 + lane*8);
            #pragma unroll
            for (int t = 0; t < 4; ++t)
                MMA_F16(acc[t][j], av[t], q.x, q.y);
        }
    };

    #pragma unroll
    for (int s = 0; s < 2; ++s) {
        if (s < NCHUNK) { cpA(s, s); cpB(s, s); }
        CP_COMMIT();
    }
    for (int c = 0; c < NCHUNK; ++c) {
        CP_WAIT1();
        __syncthreads();
        int sl = c + 2;
        if (sl < NCHUNK) { cpA(sl, sl % 3); cpB(sl, sl % 3); }
        CP_COMMIT();
        int s = c % 3;
        compute_ks(s, 0);
        compute_ks(s, 1);
    }

    const int row_base = bm + warp_m * 64 + (lane >> 2);
    const int col_base = nb * 128 + warp_n * 32 + (lane & 3) * 2;
    #pragma unroll
    for (int t = 0; t < 4; ++t) {
        int r0 = row_base + t * 16;
        int r1 = r0 + 8;
        float s0 = 1.f, s1 = 1.f;
        if (ROWSCALE) {
            s0 = (r0 < M) ? rowscale[r0] : 0.f;
            s1 = (r1 < M) ? rowscale[r1] : 0.f;
        }
        #pragma unroll
        for (int j = 0; j < 4; ++j) {
            int col = col_base + j * 8;
            float bb0 = __ldg(bias + col), bb1 = __ldg(bias + col + 1);
            float v00 = acc[t][j][0] + bb0 * s0;
            float v01 = acc[t][j][1] + bb1 * s0;
            float v10 = acc[t][j][2] + bb0 * s1;
            float v11 = acc[t][j][3] + bb1 * s1;
            if (RELU) {
                v00 = fmaxf(v00, 0.f); v01 = fmaxf(v01, 0.f);
                v10 = fmaxf(v10, 0.f); v11 = fmaxf(v11, 0.f);
            }
            if (OUTM == 1) {
                __half* Ch = (__half*)C;
                if (r0 < M) *(__half2*)(Ch + (size_t)r0 * 256 + col) =
                    __floats2half2_rn(v00, v01);
                if (r1 < M) *(__half2*)(Ch + (size_t)r1 * 256 + col) =
                    __floats2half2_rn(v10, v11);
            } else {
                float* Cf = (float*)C;
                if (r0 < M) *(float2*)(Cf + (size_t)r0 * 256 + col) = make_float2(v00, v01);
                if (r1 < M) *(float2*)(Cf + (size_t)r1 * 256 + col) = make_float2(v10, v11);
                if (OUTM == 2) {
                    if (r0 < M) *(__half2*)(C2 + (size_t)r0 * 256 + col) =
                        __floats2half2_rn(v00, v01);
                    if (r1 < M) *(__half2*)(C2 + (size_t)r1 * 256 + col) =
                        __floats2half2_rn(v10, v11);
                }
            }
        }
    }
}

// ---------------- batched 256x256x256 fp16: tmp[z] = A[z] @ Wh[14+(z&3)] -----
__global__ void __launch_bounds__(256, 2) mm256h_k(
    const __half* __restrict__ Abase, const __half* __restrict__ whbase,
    float* __restrict__ tmp)
{
    extern __shared__ char smc[];
    const uint32_t sbase = smem_u32(smc);
    const __half* A = Abase + (size_t)blockIdx.z * 65536;
    const __half* Wh = whbase + (size_t)(14 + (blockIdx.z & 3)) * 65536;
    float* C = tmp + (size_t)blockIdx.z * 65536;
    const int nb = blockIdx.y;
    const int tid = threadIdx.x;
    const int wid = tid >> 5, lane = tid & 31;
    const int warp_m = wid & 1, warp_n = wid >> 1;
    const int bm = blockIdx.x * 128;

    const int a_row = tid >> 1;
    const int a_part = tid & 1;
    const int arow = bm + a_row;
    const int a_sw = (a_row >> 1) & 3;

    float acc[4][4][4];
    #pragma unroll
    for (int t = 0; t < 4; ++t)
        #pragma unroll
        for (int j = 0; j < 4; ++j)
            #pragma unroll
            for (int q = 0; q < 4; ++q) acc[t][j][q] = 0.f;

    auto cpA = [&](int c, int s) {
        const __half* src = A + (size_t)arow * 256 + c * 32 + a_part * 16;
        uint32_t drow = sbase + s * 16384 + a_row * 64;
        #pragma unroll
        for (int j = 0; j < 2; ++j) {
            int ch = a_part * 2 + j;
            cp_async16(drow + ((ch ^ a_sw) << 4), src + j * 8);
        }
    };
    auto cpB = [&](int c, int s) {
        const __half* src = Wh + ((size_t)c * 2 + nb) * 4096 + tid * 16;
        uint32_t dst = sbase + s * 16384 + 8192 + tid * 32;
        cp_async16(dst,      src);
        cp_async16(dst + 16, src + 8);
    };
    auto compute_ks = [&](int s, int ks) {
        const char* a = smc + s * 16384;
        const char* b = smc + s * 16384 + 8192;
        const int lr = lane >> 2, lc = lane & 3;
        uint32_t av[4][4];
        #pragma unroll
        for (int t = 0; t < 4; ++t) {
            int m0 = warp_m * 64 + t * 16 + lr;
            int m1 = m0 + 8;
            int sw0 = (m0 >> 1) & 3, sw1 = (m1 >> 1) & 3;
            av[t][0] = *(const uint32_t*)(a + m0*64 + (((2*ks  ) ^ sw0) << 4) + lc*4);
            av[t][1] = *(const uint32_t*)(a + m1*64 + (((2*ks  ) ^ sw1) << 4) + lc*4);
            av[t][2] = *(const uint32_t*)(a + m0*64 + (((2*ks+1) ^ sw0) << 4) + lc*4);
            av[t][3] = *(const uint32_t*)(a + m1*64 + (((2*ks+1) ^ sw1) << 4) + lc*4);
        }
        #pragma unroll
        for (int j = 0; j < 4; ++j) {
            uint2 q = *(const uint2*)(b + (ks*16 + warp_n*4 + j) * 256 + lane*8);
            #pragma unroll
            for (int t = 0; t < 4; ++t)
                MMA_F16(acc[t][j], av[t], q.x, q.y);
        }
    };

    cpA(0, 0); cpB(0, 0); CP_COMMIT();
    cpA(1, 1); cpB(1, 1); CP_COMMIT();
    for (int c = 0; c < 8; ++c) {
        CP_WAIT1();
        __syncthreads();
        int sl = c + 2;
        if (sl < 8) { cpA(sl, sl % 3); cpB(sl, sl % 3); }
        CP_COMMIT();
        int s = c % 3;
        compute_ks(s, 0);
        compute_ks(s, 1);
    }

    const int row_base = bm + warp_m * 64 + (lane >> 2);
    const int col_base = nb * 128 + warp_n * 32 + (lane & 3) * 2;
    #pragma unroll
    for (int t = 0; t < 4; ++t) {
        int r0 = row_base + t * 16, r1 = r0 + 8;
        #pragma unroll
        for (int j = 0; j < 4; ++j) {
            int col = col_base + j * 8;
            *(float2*)(C + (size_t)r0 * 256 + col) = make_float2(acc[t][j][0], acc[t][j][1]);
            *(float2*)(C + (size_t)r1 * 256 + col) = make_float2(acc[t][j][2], acc[t][j][3]);
        }
    }
}

// ---------------- f32 -> f16 elementwise (8 per thread) ----------------------
__global__ void __launch_bounds__(256) f2h_k(
    const float* __restrict__ in, __half* __restrict__ out, int n8)
{
    int i = blockIdx.x * 256 + threadIdx.x;
    if (i >= n8) return;
    float4 a = ((const float4*)in)[i*2];
    float4 b = ((const float4*)in)[i*2+1];
    uint4 o;
    __half2* op = (__half2*)&o;
    op[0] = __floats2half2_rn(a.x, a.y);
    op[1] = __floats2half2_rn(a.z, a.w);
    op[2] = __floats2half2_rn(b.x, b.y);
    op[3] = __floats2half2_rn(b.z, b.w);
    ((uint4*)out)[i] = o;
}

// ---------------- CSR build (by dst) -----------------------------------------
__global__ void __launch_bounds__(256) hist_k(
    const int* __restrict__ eidx, int* __restrict__ cnt) {
    int i = blockIdx.x * blockDim.x + threadIdx.x;
    if (i < NE) atomicAdd(&cnt[eidx[NE + i]], 1);
}

__global__ void __launch_bounds__(256) scan1_k(
    const int* __restrict__ cnt, int* __restrict__ bs) {
    __shared__ int sm[256];
    int i = blockIdx.x * 256 + threadIdx.x;
    sm[threadIdx.x] = (i < NN) ? cnt[i] : 0;
    __syncthreads();
    #pragma unroll
    for (int o = 128; o > 0; o >>= 1) {
        if (threadIdx.x < o) sm[threadIdx.x] += sm[threadIdx.x + o];
        __syncthreads();
    }
    if (threadIdx.x == 0) bs[blockIdx.x] = sm[0];
}

__global__ void __launch_bounds__(256) scan2_k(
    int* __restrict__ bs, int* __restrict__ rp) {
    __shared__ int sm[256];
    int t = threadIdx.x;
    int v = (t < NBK) ? bs[t] : 0;
    sm[t] = v;
    __syncthreads();
    #pragma unroll
    for (int o = 1; o < 256; o <<= 1) {
        int u = (t >= o) ? sm[t - o] : 0;
        __syncthreads();
        sm[t] += u;
        __syncthreads();
    }
    if (t < NBK) bs[t] = sm[t] - v;
    if (t == NBK - 1) rp[NN] = sm[t];
}

__global__ void __launch_bounds__(256) scan3_k(
    const int* __restrict__ bs, int* __restrict__ rp, int* __restrict__ cur) {
    __shared__ int sm[256];
    int i = blockIdx.x * 256 + threadIdx.x;
    int v = (i < NN) ? cur[i] : 0;
    sm[threadIdx.x] = v;
    __syncthreads();
    #pragma unroll
    for (int o = 1; o < 256; o <<= 1) {
        int u = (threadIdx.x >= o) ? sm[threadIdx.x - o] : 0;
        __syncthreads();
        sm[threadIdx.x] += u;
        __syncthreads();
    }
    if (i < NN) {
        int off = bs[blockIdx.x] + sm[threadIdx.x] - v;
        rp[i] = off;
        cur[i] = off;
    }
}

__global__ void __launch_bounds__(256) scatter_k(
    const int* __restrict__ eidx, int* __restrict__ cur, int* __restrict__ el) {
    int e = blockIdx.x * blockDim.x + threadIdx.x;
    if (e < NE) {
        int pos = atomicAdd(&cur[eidx[NE + e]], 1);
        el[pos] = eidx[e];
    }
}

// ---------------- SpMM gather: half h -> half agg (4-edge unroll) ------------
__global__ void __launch_bounds__(256) spmm_gather_k(
    const __half* __restrict__ hh, const int* __restrict__ rp,
    const int* __restrict__ el, __half* __restrict__ agg)
{
    int n = (blockIdx.x * 256 + threadIdx.x) >> 5;
    if (n >= NN) return;
    const int lane = threadIdx.x & 31;
    const int c = lane * 8;
    int s = rp[n], e = rp[n + 1];
    float a0 = 0.f, a1 = 0.f, a2 = 0.f, a3 = 0.f;
    float a4 = 0.f, a5 = 0.f, a6 = 0.f, a7 = 0.f;
    auto addrow = [&](uint4 r) {
        __half2* p = (__half2*)&r;
        float2 f0 = __half22float2(p[0]);
        float2 f1 = __half22float2(p[1]);
        float2 f2 = __half22float2(p[2]);
        float2 f3 = __half22float2(p[3]);
        a0 += f0.x; a1 += f0.y; a2 += f1.x; a3 += f1.y;
        a4 += f2.x; a5 += f2.y; a6 += f3.x; a7 += f3.y;
    };
    int i = s;
    for (; i + 3 < e; i += 4) {
        int s0 = __ldg(el + i),     s1 = __ldg(el + i + 1);
        int s2 = __ldg(el + i + 2), s3 = __ldg(el + i + 3);
        uint4 r0 = *(const uint4*)(hh + (size_t)s0 * 256 + c);
        uint4 r1 = *(const uint4*)(hh + (size_t)s1 * 256 + c);
        uint4 r2 = *(const uint4*)(hh + (size_t)s2 * 256 + c);
        uint4 r3 = *(const uint4*)(hh + (size_t)s3 * 256 + c);
        addrow(r0); addrow(r1); addrow(r2); addrow(r3);
    }
    for (; i < e; ++i) {
        uint4 r = *(const uint4*)(hh + (size_t)__ldg(el + i) * 256 + c);
        addrow(r);
    }
    uint4 o;
    __half2* op = (__half2*)&o;
    op[0] = __floats2half2_rn(a0, a1);
    op[1] = __floats2half2_rn(a2, a3);
    op[2] = __floats2half2_rn(a4, a5);
    op[3] = __floats2half2_rn(a6, a7);
    *(uint4*)(agg + (size_t)n * 256 + c) = o;
}

// ---------------- geo stage -> half xin (4-way k unroll) ----------------------
__global__ void __launch_bounds__(256) geo_k(
    const float* __restrict__ x,
    const float* __restrict__ geo_w, const float* __restrict__ geo_b,
    __half* __restrict__ out)
{
    __shared__ float gws[4096];
    __shared__ float gbs[32];
    for (int i = threadIdx.x; i < 4096; i += 256) gws[i] = geo_w[i];
    if (threadIdx.x < 32) gbs[threadIdx.x] = geo_b[threadIdx.x];
    __syncthreads();
    const int warp = threadIdx.x >> 5, lane = threadIdx.x & 31;
    for (int n0 = blockIdx.x * 8; n0 < NN; n0 += gridDim.x * 8) {
        int n = n0 + warp;
        if (n < NN) {
            const float* xr = x + (size_t)n * 160;
            float s = gbs[lane];
            #pragma unroll
            for (int kk = 0; kk < 128; kk += 4) {
                float4 xv = *(const float4*)(xr + kk);
                s += xv.x * gws[(kk+0)*32 + lane];
                s += xv.y * gws[(kk+1)*32 + lane];
                s += xv.z * gws[(kk+2)*32 + lane];
                s += xv.w * gws[(kk+3)*32 + lane];
            }
            out[(size_t)n * 64 + lane]      = __float2half_rn(fmaxf(s, 0.f));
            out[(size_t)n * 64 + 32 + lane] = __float2half_rn(__ldg(xr + 128 + lane));
        }
    }
}

// ---------------- edge encoder + scatter (fp32, 16 edges per sync) -----------
__global__ void __launch_bounds__(256) edge_encode_k(
    const float* __restrict__ ea, const int* __restrict__ eidx,
    const float* __restrict__ w1, const float* __restrict__ b1,
    float* __restrict__ At, float* __restrict__ deg)
{
    const int tid = threadIdx.x;
    const int c0 = (tid & 63) * 4;
    const int slot = tid >> 6;
    float4 wreg[16];
    #pragma unroll
    for (int k = 0; k < 16; ++k)
        wreg[k] = *(const float4*)(w1 + k * 256 + c0);
    const float4 b1v = *(const float4*)(b1 + c0);

    __shared__ float eav[16][16];
    __shared__ int dsts[16];

    for (int base = blockIdx.x * 16; base < NE; base += gridDim.x * 16) {
        ((float*)eav)[tid] = ea[(size_t)base * 16 + tid];
        if (tid < 16) dsts[tid] = eidx[NE + base + tid];
        __syncthreads();
        #pragma unroll
        for (int g = 0; g < 4; ++g) {
            const int e = slot + g * 4;
            float4 acc = b1v;
            #pragma unroll
            for (int k = 0; k < 16; ++k) {
                float ev = eav[e][k];
                acc.x += wreg[k].x * ev;
                acc.y += wreg[k].y * ev;
                acc.z += wreg[k].z * ev;
                acc.w += wreg[k].w * ev;
            }
            acc.x = fmaxf(acc.x, 0.f); acc.y = fmaxf(acc.y, 0.f);
            acc.z = fmaxf(acc.z, 0.f); acc.w = fmaxf(acc.w, 0.f);
            int dst = dsts[e];
            redAdd4(At + (size_t)dst * 256 + c0, acc);
            if ((tid & 63) == 0) atomicAdd(deg + dst, 1.f);
        }
        __syncthreads();
    }
}

// ---------------- residual + layernorm (fp32 h, half u) ----------------------
__global__ void __launch_bounds__(256) ln_k(
    const float* h, const __half* __restrict__ u,
    const float* __restrict__ g, const float* __restrict__ b,
    float* o, __half* oh)
{
    int gw = (blockIdx.x*blockDim.x + threadIdx.x) >> 5;
    int lane = threadIdx.x & 31;
    int nw = (gridDim.x*blockDim.x) >> 5;
    for (int n = gw; n < NN; n += nw) {
        const float* hp = h + (size_t)n*256;
        float v[8];
        float4 h0 = *(const float4*)(hp + lane*8), h1 = *(const float4*)(hp + lane*8 + 4);
        uint4 ur = *(const uint4*)(u + (size_t)n*256 + lane*8);
        __half2* up = (__half2*)&ur;
        float2 u0 = __half22float2(up[0]);
        float2 u1 = __half22float2(up[1]);
        float2 u2 = __half22float2(up[2]);
        float2 u3 = __half22float2(up[3]);
        v[0]=h0.x+u0.x; v[1]=h0.y+u0.y; v[2]=h0.z+u1.x; v[3]=h0.w+u1.y;
        v[4]=h1.x+u2.x; v[5]=h1.y+u2.y; v[6]=h1.z+u3.x; v[7]=h1.w+u3.y;
        float s = 0.f;
        #pragma unroll
        for (int i = 0; i < 8; ++i) s += v[i];
        #pragma unroll
        for (int oo = 16; oo > 0; oo >>= 1) s += __shfl_xor_sync(0xffffffffu, s, oo);
        float mu = s * (1.f/256.f);
        float qq = 0.f;
        #pragma unroll
        for (int i = 0; i < 8; ++i) { float d = v[i]-mu; qq += d*d; }
        #pragma unroll
        for (int oo = 16; oo > 0; oo >>= 1) qq += __shfl_xor_sync(0xffffffffu, qq, oo);
        float rstd = rsqrtf(qq*(1.f/256.f) + 1e-5f);
        #pragma unroll
        for (int i = 0; i < 8; ++i) {
            int c = lane*8 + i;
            v[i] = (v[i]-mu)*rstd*__ldg(g+c) + __ldg(b+c);
        }
        float* op = o + (size_t)n*256;
        *(float4*)(op + lane*8)     = make_float4(v[0],v[1],v[2],v[3]);
        *(float4*)(op + lane*8 + 4) = make_float4(v[4],v[5],v[6],v[7]);
        if (oh) {
            uint4 w;
            __half2* wp = (__half2*)&w;
            wp[0] = __floats2half2_rn(v[0], v[1]);
            wp[1] = __floats2half2_rn(v[2], v[3]);
            wp[2] = __floats2half2_rn(v[4], v[5]);
            wp[3] = __floats2half2_rn(v[6], v[7]);
            *(uint4*)(oh + (size_t)n*256 + lane*8) = w;
        }
    }
}

// ---------------- typed mean-pool partial sums -------------------------------
__global__ void __launch_bounds__(256) pool_k(
    const float* __restrict__ h, const int* __restrict__ batch,
    const int* __restrict__ ntype, float* __restrict__ ps, float* __restrict__ pc)
{
    __shared__ float acc[24][256];
    __shared__ float cnt[24];
    for (int i = threadIdx.x; i < 24*256; i += 256) (&acc[0][0])[i] = 0.f;
    if (threadIdx.x < 24) cnt[threadIdx.x] = 0.f;
    __syncthreads();
    int per = (NN + gridDim.x - 1) / gridDim.x;
    int start = blockIdx.x * per;
    int end = start + per; if (end > NN) end = NN;
    for (int n = start; n < end; ++n) {
        int idx = __ldg(ntype+n)*8 + __ldg(batch+n);
        acc[idx][threadIdx.x] += h[(size_t)n*256 + threadIdx.x];
        if (threadIdx.x == 0) cnt[idx] += 1.f;
    }
    __syncthreads();
    for (int i = threadIdx.x; i < 24*256; i += 256) atomicAdd(&ps[i], (&acc[0][0])[i]);
    if (threadIdx.x < 24) atomicAdd(&pc[threadIdx.x], cnt[threadIdx.x]);
}

// ---------------- small writeout: z + batch only ------------------------------
__global__ void __launch_bounds__(256) writeout_small_k(
    const float* __restrict__ ps, const float* __restrict__ pc,
    const int* __restrict__ batch, float* __restrict__ out, int out_size)
{
    const int total = 6144 + NN;
    int i = blockIdx.x * blockDim.x + threadIdx.x;
    if (i >= total) return;
    float v; int o;
    if (i < 6144) {
        int c = i & 255, kb = i >> 8, k = kb >> 3, bb = kb & 7;
        float cc = pc[kb]; if (cc < 1.f) cc = 1.f;
        v = ps[i] / cc;
        o = bb*768 + k*256 + c;
    } else {
        v = (float)batch[i - 6144];
        o = 6144 + NN*HD + (i - 6144);
    }
    if (o < out_size) out[o] = v;
}

// ---------------- launcher ----------------------------------------------------
extern "C" void kernel_launch(void* const* d_in, const int* in_sizes, int n_in,
                              void* d_out, int out_size)
{
    const float* x       = (const float*)d_in[0];
    const float* ea      = (const float*)d_in[1];
    const float* geo_w   = (const float*)d_in[2];
    const float* geo_b   = (const float*)d_in[3];
    const float* nin_w1  = (const float*)d_in[4];
    const float* nin_b1  = (const float*)d_in[5];
    const float* nin_w2  = (const float*)d_in[6];
    const float* nin_b2  = (const float*)d_in[7];
    const float* ee_w1   = (const float*)d_in[8];
    const float* ee_b1   = (const float*)d_in[9];
    const float* ee_w2   = (const float*)d_in[10];
    const float* ee_b2   = (const float*)d_in[11];
    const float* msgx    = (const float*)d_in[12];
    const float* msge    = (const float*)d_in[13];
    const float* upd_w1  = (const float*)d_in[14];
    const float* upd_b1  = (const float*)d_in[15];
    const float* upd_w2  = (const float*)d_in[16];
    const float* upd_b2  = (const float*)d_in[17];
    const float* ln_g    = (const float*)d_in[18];
    const float* ln_b    = (const float*)d_in[19];
    const int*   eidx    = (const int*)d_in[20];
    const int*   batch   = (const int*)d_in[21];
    const int*   ntype   = (const int*)d_in[22];
    float* out = (float*)d_out;

    float *h_, *d2f_, *deg_, *ps_, *pc_;
    __half *hh_, *d1h_, *d3h_, *aeh_, *xinh_, *wth_, *wt1h_;
    int *rp_, *cur_, *el_, *bs_;
    cudaGetSymbolAddress((void**)&h_,   g_h);
    cudaGetSymbolAddress((void**)&hh_,  g_hh);
    cudaGetSymbolAddress((void**)&d2f_, g_d2f);
    cudaGetSymbolAddress((void**)&deg_, g_deg);
    cudaGetSymbolAddress((void**)&ps_,  g_ps);
    cudaGetSymbolAddress((void**)&pc_,  g_pc);
    cudaGetSymbolAddress((void**)&d1h_, g_d1h);
    cudaGetSymbolAddress((void**)&d3h_, g_d3h);
    cudaGetSymbolAddress((void**)&aeh_, g_aeh);
    cudaGetSymbolAddress((void**)&xinh_, g_xinh);
    cudaGetSymbolAddress((void**)&wth_, g_wth);
    cudaGetSymbolAddress((void**)&wt1h_, g_wt1h);
    cudaGetSymbolAddress((void**)&rp_,  g_rp);
    cudaGetSymbolAddress((void**)&cur_, g_cur);
    cudaGetSymbolAddress((void**)&el_,  g_el);
    cudaGetSymbolAddress((void**)&bs_,  g_bs);

    cudaFuncSetAttribute((const void*)mm256h_k,
        cudaFuncAttributeMaxDynamicSharedMemorySize, GEMM_H_SMEM);
    cudaFuncSetAttribute((const void*)gemm_h<64,false,true,1,false>,
        cudaFuncAttributeMaxDynamicSharedMemorySize, GEMM_H_SMEM);
    cudaFuncSetAttribute((const void*)gemm_h<256,false,false,2,false>,
        cudaFuncAttributeMaxDynamicSharedMemorySize, GEMM_H_SMEM);
    cudaFuncSetAttribute((const void*)gemm_h<256,false,false,1,true>,
        cudaFuncAttributeMaxDynamicSharedMemorySize, GEMM_H_SMEM);
    cudaFuncSetAttribute((const void*)gemm_h<256,true,true,1,false>,
        cudaFuncAttributeMaxDynamicSharedMemorySize, GEMM_H_SMEM);
    cudaFuncSetAttribute((const void*)gemm_h<256,false,false,1,false>,
        cudaFuncAttributeMaxDynamicSharedMemorySize, GEMM_H_SMEM);

    // --- weight precompute (all fp16) ------------------------------------------
    // upd_w1 -> half frags in slots 14..17
    WPtrs wpu;
    for (int l = 0; l < 4; ++l) wpu.p[l] = upd_w1 + (size_t)l*65536;
    wfrag_h_k<<<dim3(16, 4), 256>>>(wpu, wth_ + (size_t)14*65536);

    // msgx|msge -> half row-major staging in d3h
    f2h_k<<<128, 256>>>(msgx, d3h_, 32768);
    f2h_k<<<128, 256>>>(msge, d3h_ + (size_t)4*65536, 32768);

    // M1/E1 = (msgx|msge)[l] @ upd_w1[l]  (fp16 mma, fp32 out -> d2f)
    mm256h_k<<<dim3(2, 2, 8), 256, GEMM_H_SMEM>>>(d3h_, wth_, d2f_);

    // production half frags: 0 nin_w2, 1..4 M1, 5..8 E1, 9..12 upd_w2, 13 ee_w2
    WPtrs wph;
    wph.p[0] = nin_w2;
    for (int l = 0; l < 4; ++l) {
        wph.p[1 + l] = d2f_ + (size_t)l*65536;
        wph.p[5 + l] = d2f_ + (size_t)(4+l)*65536;
        wph.p[9 + l] = upd_w2 + (size_t)l*65536;
    }
    wph.p[13] = ee_w2;
    wfrag_h_k<<<dim3(16, 14), 256>>>(wph, wth_);
    wfrag64_h_k<<<4, 256>>>(nin_w1, wt1h_);

    // --- CSR build (by dst) -----------------------------------------------------
    cudaMemsetAsync(cur_, 0, NN*sizeof(int));
    hist_k<<<(NE+255)/256, 256>>>(eidx, cur_);
    scan1_k<<<NBK, 256>>>(cur_, bs_);
    scan2_k<<<1, 256>>>(bs_, rp_);
    scan3_k<<<NBK, 256>>>(bs_, rp_, cur_);
    scatter_k<<<(NE+255)/256, 256>>>(eidx, cur_, el_);

    dim3 gg(391, 2);

    // node encoder
    geo_k<<<625, 256>>>(x, geo_w, geo_b, xinh_);
    gemm_h<64,false,true,1,false><<<gg, 256, GEMM_H_SMEM>>>(
        xinh_, wt1h_, nullptr, nullptr, nin_b1, nullptr, d1h_, nullptr, NN);
    gemm_h<256,false,false,2,false><<<gg, 256, GEMM_H_SMEM>>>(
        d1h_, wth_ + (size_t)0*65536, nullptr, nullptr, nin_b2, nullptr,
        h_, hh_, NN);

    // edge encoder scatter (fp32) -> convert to half -> ee GEMM -> aeh
    cudaMemsetAsync(d2f_, 0, (size_t)NN*HD*sizeof(float));
    cudaMemsetAsync(deg_, 0, (size_t)NN*sizeof(float));
    edge_encode_k<<<1184, 256>>>(ea, eidx, ee_w1, ee_b1, d2f_, deg_);
    f2h_k<<<(NN*HD/8+255)/256, 256>>>(d2f_, d1h_, NN*HD/8);
    gemm_h<256,false,false,1,true><<<gg, 256, GEMM_H_SMEM>>>(
        d1h_, wth_ + (size_t)13*65536, nullptr, nullptr, ee_b2, deg_,
        aeh_, nullptr, NN);

    float* hout = out + 6144;
    for (int l = 0; l < NL; ++l) {
        spmm_gather_k<<<6250, 256>>>(hh_, rp_, el_, d1h_);
        // d3h = relu(Ah@M1 + Ae@E1 + b1)
        gemm_h<256,true,true,1,false><<<gg, 256, GEMM_H_SMEM>>>(
            d1h_, wth_ + (size_t)(1+l)*65536, aeh_, wth_ + (size_t)(5+l)*65536,
            upd_b1 + l*256, nullptr, d3h_, nullptr, NN);
        // u = d3h@upd_w2 + b2 (half out, reuses d1h)
        gemm_h<256,false,false,1,false><<<gg, 256, GEMM_H_SMEM>>>(
            d3h_, wth_ + (size_t)(9+l)*65536, nullptr, nullptr,
            upd_b2 + l*256, nullptr, d1h_, nullptr, NN);
        // h = LN(h + u); layers 0-2 also write half mirror
        ln_k<<<784, 256>>>(h_, d1h_, ln_g + l*256, ln_b + l*256,
                           (l == NL-1) ? hout : h_,
                           (l == NL-1) ? nullptr : hh_);
    }

    cudaMemsetAsync(ps_, 0, 24*HD*sizeof(float));
    cudaMemsetAsync(pc_, 0, 24*sizeof(float));
    pool_k<<<512, 256>>>(hout, batch, ntype, ps_, pc_);
    writeout_small_k<<<(6144+NN+255)/256, 256>>>(ps_, pc_, batch, out, out_size);
}